// round 1
// baseline (speedup 1.0000x reference)
#include <cuda_runtime.h>
#include <math.h>

#define TT   32768
#define CC   512
#define EE   8
#define HH   16
#define BB   8
#define NNN  4096
#define TSTR 516   // padded tile row stride (float4-aligned, decent bank spread)

// ---------------- scratch (static device globals; no allocation) -------------
__device__ float g_h[(size_t)TT * CC];   // gate hidden, 64MB
__device__ int   g_re[TT * 2];           // top-2 expert ids
__device__ float g_rw[TT * 2];           // top-2 softmax weights
__device__ float g_sum[CC];
__device__ float g_sumsq[CC];
__device__ float g_usage[EE];

// ---------------- zero accumulators ------------------------------------------
__global__ void k_zero() {
    int i = threadIdx.x;
    if (i < CC) { g_sum[i] = 0.f; g_sumsq[i] = 0.f; }
    if (i < EE) g_usage[i] = 0.f;
}

// ---------------- gate GEMM1: h = x @ wg1^T + bg1  (fp32, exact path) --------
// M=32768, N=512, K=512. 64x64 tile, BK=32, 256 thr, 4x4 microtile.
__global__ __launch_bounds__(256) void k_gemm1(const float* __restrict__ x,
                                               const float* __restrict__ wg1,
                                               const float* __restrict__ bg1) {
    __shared__ float As[64][33];
    __shared__ float Bs[64][33];
    int tid = threadIdx.x;
    int m0 = blockIdx.y * 64;
    int n0 = blockIdx.x * 64;
    int tx = tid & 15, ty = tid >> 4;

    float acc[4][4];
#pragma unroll
    for (int i = 0; i < 4; i++)
#pragma unroll
        for (int j = 0; j < 4; j++) acc[i][j] = 0.f;

    for (int k0 = 0; k0 < CC; k0 += 32) {
#pragma unroll
        for (int l = 0; l < 2; l++) {
            int idx = tid + l * 256;
            int r = idx >> 3;
            int c4 = (idx & 7) << 2;
            float4 va = *(const float4*)(x + (size_t)(m0 + r) * CC + k0 + c4);
            As[r][c4] = va.x; As[r][c4 + 1] = va.y; As[r][c4 + 2] = va.z; As[r][c4 + 3] = va.w;
            float4 vb = *(const float4*)(wg1 + (size_t)(n0 + r) * CC + k0 + c4);
            Bs[r][c4] = vb.x; Bs[r][c4 + 1] = vb.y; Bs[r][c4 + 2] = vb.z; Bs[r][c4 + 3] = vb.w;
        }
        __syncthreads();
#pragma unroll
        for (int kk = 0; kk < 32; kk++) {
            float a[4], b[4];
#pragma unroll
            for (int i = 0; i < 4; i++) a[i] = As[ty * 4 + i][kk];
#pragma unroll
            for (int j = 0; j < 4; j++) b[j] = Bs[tx * 4 + j][kk];
#pragma unroll
            for (int i = 0; i < 4; i++)
#pragma unroll
                for (int j = 0; j < 4; j++) acc[i][j] += a[i] * b[j];
        }
        __syncthreads();
    }
#pragma unroll
    for (int i = 0; i < 4; i++) {
        size_t row = (size_t)(m0 + ty * 4 + i) * CC;
#pragma unroll
        for (int j = 0; j < 4; j++) {
            int col = n0 + tx * 4 + j;
            g_h[row + col] = acc[i][j] + bg1[col];
        }
    }
}

// ---------------- BN batch stats ---------------------------------------------
__global__ __launch_bounds__(512) void k_bnstats() {
    int c = threadIdx.x;
    int t0 = blockIdx.x * 128;
    float s = 0.f, s2 = 0.f;
    for (int t = 0; t < 128; t++) {
        float v = g_h[(size_t)(t0 + t) * CC + c];
        s += v; s2 += v * v;
    }
    atomicAdd(&g_sum[c], s);
    atomicAdd(&g_sumsq[c], s2);
}

// ---------------- BN + ReLU + gate GEMM2 + top-2 softmax routing -------------
__global__ __launch_bounds__(256) void k_route(const float* __restrict__ gamma,
                                               const float* __restrict__ beta,
                                               const float* __restrict__ wg2,
                                               const float* __restrict__ bg2) {
    __shared__ float wg2s[EE][CC];
    __shared__ float mus[CC], rss[CC];
    int tid = threadIdx.x;
    for (int idx = tid; idx < EE * CC; idx += 256) ((float*)wg2s)[idx] = wg2[idx];
    for (int c = tid; c < CC; c += 256) {
        float m = g_sum[c] * (1.0f / TT);
        float v = g_sumsq[c] * (1.0f / TT) - m * m;
        mus[c] = m;
        rss[c] = rsqrtf(v + 1e-5f);
    }
    __syncthreads();

    int warp = tid >> 5, lane = tid & 31;
    int t = blockIdx.x * 8 + warp;

    float p[EE];
#pragma unroll
    for (int e = 0; e < EE; e++) p[e] = 0.f;

    for (int i = 0; i < 16; i++) {
        int c = lane + i * 32;
        float v = g_h[(size_t)t * CC + c];
        float r = fmaxf(gamma[c] * (v - mus[c]) * rss[c] + beta[c], 0.f);
#pragma unroll
        for (int e = 0; e < EE; e++) p[e] += r * wg2s[e][c];
    }
#pragma unroll
    for (int e = 0; e < EE; e++)
        for (int off = 16; off; off >>= 1) p[e] += __shfl_xor_sync(0xffffffffu, p[e], off);

    if (lane == 0) {
        float l[EE];
#pragma unroll
        for (int e = 0; e < EE; e++) l[e] = p[e] + bg2[e];
        // top-2 with first-occurrence tie break (matches jax top_k)
        int e0 = 0; float v0 = l[0];
#pragma unroll
        for (int e = 1; e < EE; e++) if (l[e] > v0) { v0 = l[e]; e0 = e; }
        int e1 = -1; float v1 = -1e30f;
#pragma unroll
        for (int e = 0; e < EE; e++) if (e != e0 && l[e] > v1) { v1 = l[e]; e1 = e; }
        float ex = expf(v1 - v0);
        float inv = 1.f / (1.f + ex);
        float w0 = inv, w1 = ex * inv;
        g_re[t * 2] = e0; g_re[t * 2 + 1] = e1;
        g_rw[t * 2] = w0; g_rw[t * 2 + 1] = w1;
        atomicAdd(&g_usage[e0], w0);
        atomicAdd(&g_usage[e1], w1);
    }
}

// ---------------- experts + weighted combine + transpose ---------------------
// One block = 64 tokens (within one batch element). All weight traffic via smem.
__global__ __launch_bounds__(256) void k_expert(const float* __restrict__ x,
                                                const float* __restrict__ w1,
                                                const float* __restrict__ b1,
                                                const float* __restrict__ w2,
                                                const float* __restrict__ b2,
                                                float* __restrict__ out) {
    extern __shared__ float sm[];
    float* tile = sm;                    // 64*TSTR : x tile, later out tile
    float* wbuf = sm + 64 * TSTR;        // 8192    : w1[e] / w2[e]
    float* h1s  = wbuf + 8192;           // 64*32   : hidden activations
    float* b2s  = h1s + 2048;            // 512

    __shared__ int cnt[EE];
    __shared__ unsigned char lst[EE][64];
    __shared__ float rw[128];

    int tid = threadIdx.x;
    int tg0 = blockIdx.x * 64;
    int bidx = tg0 >> 12;         // N=4096 tokens per batch
    int n0 = tg0 & (NNN - 1);

    // phase A: stage x tile (float4 coalesced), build per-expert token lists
    for (int idx = tid; idx < 64 * 128; idx += 256) {
        int t = idx >> 7;
        int c = (idx & 127) << 2;
        float4 v = *(const float4*)(x + (size_t)(tg0 + t) * CC + c);
        *(float4*)(tile + t * TSTR + c) = v;
    }
    if (tid < EE) cnt[tid] = 0;
    __syncthreads();
    if (tid < 128) {
        int t = tid >> 1, s = tid & 1;
        int e = g_re[(tg0 + t) * 2 + s];
        rw[tid] = g_rw[(tg0 + t) * 2 + s];
        int p = atomicAdd(&cnt[e], 1);
        lst[e][p] = (unsigned char)tid;
    }
    __syncthreads();

    // phase B: h1 = relu(x @ w1[e] + b1[e]) for routed (token, slot)
    int h = tid & 15, j = tid >> 4;
    for (int e = 0; e < EE; e++) {
        for (int idx = tid; idx < CC * HH; idx += 256) wbuf[idx] = w1[e * CC * HH + idx];
        __syncthreads();
        int m = cnt[e];
        float bb = b1[e * HH + h];
        for (int base = 0; base < m; base += 16) {
            int ii = base + j;
            if (ii < m) {
                int ts = lst[e][ii];
                int t = ts >> 1, slot = ts & 1;
                const float* xr = tile + t * TSTR;
                float acc = 0.f;
#pragma unroll 8
                for (int c = 0; c < CC; c += 4) {
                    float4 xv = *(const float4*)(xr + c);
                    acc += xv.x * wbuf[c * 16 + h];
                    acc += xv.y * wbuf[(c + 1) * 16 + h];
                    acc += xv.z * wbuf[(c + 2) * 16 + h];
                    acc += xv.w * wbuf[(c + 3) * 16 + h];
                }
                h1s[t * 32 + slot * 16 + h] = fmaxf(acc + bb, 0.f);
            }
        }
        __syncthreads();
    }

    // reuse tile as out accumulator
    for (int idx = tid; idx < 64 * TSTR; idx += 256) tile[idx] = 0.f;
    __syncthreads();

    // phase C: out[t] += w * (h1 @ w2[e] + b2[e])
    for (int e = 0; e < EE; e++) {
        for (int idx = tid; idx < HH * CC; idx += 256) wbuf[idx] = w2[e * HH * CC + idx];
        for (int idx = tid; idx < CC; idx += 256) b2s[idx] = b2[e * CC + idx];
        __syncthreads();
        int m = cnt[e];
        for (int ii = 0; ii < m; ii++) {
            int ts = lst[e][ii];
            int t = ts >> 1, slot = ts & 1;
            float w = rw[ts];
            const float* hh = h1s + t * 32 + slot * 16;
            float hr[16];
#pragma unroll
            for (int k = 0; k < 16; k++) hr[k] = hh[k];
            for (int c = tid; c < CC; c += 256) {
                float acc = b2s[c];
#pragma unroll
                for (int k = 0; k < 16; k++) acc += hr[k] * wbuf[k * CC + c];
                tile[t * TSTR + c] += w * acc;
            }
        }
        __syncthreads();
    }

    // phase D: coalesced transposed write: out[b][c][n0 + t]
    int t = tid & 63, c0 = tid >> 6;
    float* ob = out + (size_t)bidx * CC * NNN + n0 + t;
    for (int c = c0; c < CC; c += 4) ob[(size_t)c * NNN] = tile[t * TSTR + c];
}

// ---------------- load-balance loss -------------------------------------------
__global__ void k_lb(float* __restrict__ out, long long out_size) {
    if (threadIdx.x == 0 && out_size > (long long)BB * CC * NNN) {
        float s = 0.f;
#pragma unroll
        for (int e = 0; e < EE; e++) {
            float u = g_usage[e] * (1.0f / TT);
            s += u * u;
        }
        out[(size_t)BB * CC * NNN] = s * (float)EE;
    }
}

// ---------------- launch --------------------------------------------------------
extern "C" void kernel_launch(void* const* d_in, const int* in_sizes, int n_in,
                              void* d_out, int out_size) {
    const float* x     = (const float*)d_in[0];
    const float* wg1   = (const float*)d_in[1];
    const float* bg1   = (const float*)d_in[2];
    const float* gamma = (const float*)d_in[3];
    const float* beta  = (const float*)d_in[4];
    const float* wg2   = (const float*)d_in[5];
    const float* bg2   = (const float*)d_in[6];
    const float* w1    = (const float*)d_in[7];
    const float* b1    = (const float*)d_in[8];
    const float* w2    = (const float*)d_in[9];
    const float* b2    = (const float*)d_in[10];
    float* out = (float*)d_out;

    int smem = (64 * TSTR + 8192 + 2048 + 512) * (int)sizeof(float);  // 175104 B
    cudaFuncSetAttribute(k_expert, cudaFuncAttributeMaxDynamicSharedMemorySize, smem);

    k_zero<<<1, 512>>>();
    dim3 g1(CC / 64, TT / 64);
    k_gemm1<<<g1, 256>>>(x, wg1, bg1);
    k_bnstats<<<TT / 128, 512>>>();
    k_route<<<TT / 8, 256>>>(gamma, beta, wg2, bg2);
    k_expert<<<TT / 64, 256, smem>>>(x, w1, b1, w2, b2, out);
    k_lb<<<1, 32>>>(out, (long long)out_size);
}

// round 3
// speedup vs baseline: 1.2241x; 1.2241x over previous
#include <cuda_runtime.h>
#include <cuda_bf16.h>
#include <math.h>
#include <stdint.h>

#define TT   32768
#define CC   512
#define EE   8
#define HH   16
#define BB   8
#define NNN  4096
#define TSTR 516
#define FIXCAP 8192

// ---------------- scratch (static device globals; no allocation) -------------
__device__ float g_h[(size_t)TT * CC];     // gate hidden, 64MB
__device__ int   g_re[TT * 2];
__device__ float g_rw[TT * 2];
__device__ float g_sum[CC];
__device__ float g_sumsq[CC];
__device__ float g_usage[EE];
__device__ int   g_nfix;
__device__ int   g_fix[FIXCAP];
__device__ __align__(16) __nv_bfloat16 g_xh[(size_t)TT * CC];
__device__ __align__(16) __nv_bfloat16 g_xl[(size_t)TT * CC];
__device__ __align__(16) __nv_bfloat16 g_wh[CC * CC];
__device__ __align__(16) __nv_bfloat16 g_wl[CC * CC];

// ---------------- PTX helpers (non-'a' target safe: ldmatrix + mma.sync) -----
__device__ __forceinline__ uint32_t smem_u32(const void* p) {
    uint32_t a;
    asm("{ .reg .u64 t; cvta.to.shared.u64 t, %1; cvt.u32.u64 %0, t; }" : "=r"(a) : "l"(p));
    return a;
}
__device__ __forceinline__ void ldm4(uint32_t* r, uint32_t a) {
    asm volatile("ldmatrix.sync.aligned.m8n8.x4.shared.b16 {%0,%1,%2,%3}, [%4];"
                 : "=r"(r[0]), "=r"(r[1]), "=r"(r[2]), "=r"(r[3]) : "r"(a));
}
__device__ __forceinline__ void mma16816(float* d, const uint32_t* a,
                                         uint32_t b0, uint32_t b1) {
    asm volatile(
        "mma.sync.aligned.m16n8k16.row.col.f32.bf16.bf16.f32 "
        "{%0,%1,%2,%3}, {%4,%5,%6,%7}, {%8,%9}, {%0,%1,%2,%3};"
        : "+f"(d[0]), "+f"(d[1]), "+f"(d[2]), "+f"(d[3])
        : "r"(a[0]), "r"(a[1]), "r"(a[2]), "r"(a[3]), "r"(b0), "r"(b1));
}

// ---------------- zero accumulators ------------------------------------------
__global__ void k_zero() {
    int i = threadIdx.x;
    if (i < CC) { g_sum[i] = 0.f; g_sumsq[i] = 0.f; }
    if (i < EE) g_usage[i] = 0.f;
    if (i == 0) g_nfix = 0;
}

// ---------------- bf16 hi/lo split of x and wg1 ------------------------------
__global__ __launch_bounds__(256) void k_split(const float* __restrict__ x,
                                               const float* __restrict__ wg1) {
    size_t i4 = (size_t)blockIdx.x * 256 + threadIdx.x;
    const size_t nx = (size_t)TT * CC / 4, nw = (size_t)CC * CC / 4;
    const float* s; __nv_bfloat16 *dh, *dl; size_t o;
    if (i4 < nx)           { s = x;   o = i4;      dh = g_xh; dl = g_xl; }
    else if (i4 < nx + nw) { s = wg1; o = i4 - nx; dh = g_wh; dl = g_wl; }
    else return;
    float4 v = ((const float4*)s)[o];
    float a[4] = {v.x, v.y, v.z, v.w};
    unsigned hh[4], ll[4];
#pragma unroll
    for (int i = 0; i < 4; i++) {
        __nv_bfloat16 hb = __float2bfloat16(a[i]);
        __nv_bfloat16 lb = __float2bfloat16(a[i] - __bfloat162float(hb));
        hh[i] = ((__nv_bfloat16_raw)hb).x;
        ll[i] = ((__nv_bfloat16_raw)lb).x;
    }
    uint2 ph = {hh[0] | (hh[1] << 16), hh[2] | (hh[3] << 16)};
    uint2 pl = {ll[0] | (ll[1] << 16), ll[2] | (ll[3] << 16)};
    ((uint2*)dh)[o] = ph;
    ((uint2*)dl)[o] = pl;
}

// ---------------- gate GEMM1 via mma.sync (HMMA): h = x @ wg1^T + bg1 --------
// 3-term bf16 split. Block tile 128x128, BK=64 (128B SW128 rows).
// 8 warps, warp tile 32x64: 2 (m16) x 8 (n8) HMMA per k16.
#define GSMEM 65536

__global__ __launch_bounds__(256, 2) void k_gemm(const float* __restrict__ bg1) {
    extern __shared__ char smc[];
    uint32_t sb = smem_u32(smc);
    int tid = threadIdx.x;
    int n0 = blockIdx.x * 128, m0 = blockIdx.y * 128;
    int warp = tid >> 5, lane = tid & 31;
    int wm = warp >> 1, wn = warp & 1;

    float acc[2][8][4];
#pragma unroll
    for (int i = 0; i < 2; i++)
#pragma unroll
        for (int j = 0; j < 8; j++)
#pragma unroll
            for (int q = 0; q < 4; q++) acc[i][j][q] = 0.f;

    // ldmatrix lane addressing
    int li = lane & 7, lm = lane >> 3;
    int a_row = (lm & 1) * 8 + li, a_cb = (lm >> 1) * 16;   // A frag order a0..a3
    int b_row = (lm >> 1) * 8 + li, b_cb = (lm & 1) * 16;   // B: two n8 tiles per x4

    const __nv_bfloat16* gp[4] = {g_xh, g_xl, g_wh, g_wl};
    const int rb[4] = {m0, m0, n0, n0};

    for (int kc = 0; kc < 8; kc++) {
        int k0 = kc * 64;
#pragma unroll
        for (int tt = 0; tt < 4; tt++) {
            const __nv_bfloat16* src = gp[tt];
            char* dst = smc + tt * 16384;
            int rbase = rb[tt];
#pragma unroll
            for (int it = 0; it < 8; it++) {
                int idx = tid + it * 256;
                int r = idx >> 4, c4 = (idx & 15) << 2;
                uint2 v = *(const uint2*)(src + (size_t)(rbase + r) * CC + k0 + c4);
                uint32_t bo = (r << 7) + (c4 << 1);
                bo ^= (bo >> 3) & 0x70;
                *(uint2*)(dst + bo) = v;
            }
        }
        __syncthreads();

        // three term pairs: (Ah,Bh), (Ah,Bl), (Al,Bh)
#pragma unroll
        for (int tp = 0; tp < 3; tp++) {
            uint32_t abase = sb + ((tp == 2) ? 16384 : 0);
            uint32_t bbase = sb + 32768 + ((tp == 1) ? 16384 : 0);
#pragma unroll
            for (int ks = 0; ks < 4; ks++) {
                int kb = ks * 32;
                uint32_t af[2][4];
#pragma unroll
                for (int mi = 0; mi < 2; mi++) {
                    int r = wm * 32 + mi * 16 + a_row;
                    uint32_t cb = (uint32_t)(kb + a_cb);
                    uint32_t addr = abase + (r << 7) + (cb ^ ((r & 7) << 4));
                    ldm4(af[mi], addr);
                }
                uint32_t bfr[4][4];
#pragma unroll
                for (int p = 0; p < 4; p++) {
                    int r = wn * 64 + p * 16 + b_row;
                    uint32_t cb = (uint32_t)(kb + b_cb);
                    uint32_t addr = bbase + (r << 7) + (cb ^ ((r & 7) << 4));
                    ldm4(bfr[p], addr);
                }
#pragma unroll
                for (int mi = 0; mi < 2; mi++)
#pragma unroll
                    for (int ni = 0; ni < 8; ni++)
                        mma16816(acc[mi][ni], af[mi],
                                 bfr[ni >> 1][(ni & 1) * 2],
                                 bfr[ni >> 1][(ni & 1) * 2 + 1]);
            }
        }
        __syncthreads();
    }

    // epilogue: h = acc + bias
    int g = lane >> 2, tg = lane & 3;
#pragma unroll
    for (int mi = 0; mi < 2; mi++) {
        int row = m0 + wm * 32 + mi * 16 + g;
#pragma unroll
        for (int ni = 0; ni < 8; ni++) {
            int col = n0 + wn * 64 + ni * 8 + tg * 2;
            float bx = bg1[col], by = bg1[col + 1];
            float2 v0 = {acc[mi][ni][0] + bx, acc[mi][ni][1] + by};
            float2 v1 = {acc[mi][ni][2] + bx, acc[mi][ni][3] + by};
            *(float2*)(g_h + (size_t)row * CC + col) = v0;
            *(float2*)(g_h + (size_t)(row + 8) * CC + col) = v1;
        }
    }
}

// ---------------- BN batch stats ---------------------------------------------
__global__ __launch_bounds__(512) void k_bnstats() {
    int c = threadIdx.x;
    int t0 = blockIdx.x * 128;
    float s = 0.f, s2 = 0.f;
    for (int t = 0; t < 128; t++) {
        float v = g_h[(size_t)(t0 + t) * CC + c];
        s += v; s2 += v * v;
    }
    atomicAdd(&g_sum[c], s);
    atomicAdd(&g_sumsq[c], s2);
}

// ---------------- BN + ReLU + gate GEMM2 + top-2 routing (tiled) -------------
#define RSTR 516
__global__ __launch_bounds__(256) void k_route(const float* __restrict__ gamma,
                                               const float* __restrict__ beta,
                                               const float* __restrict__ wg2,
                                               const float* __restrict__ bg2) {
    extern __shared__ float dynsm[];
    float* hs  = dynsm;                 // 32*516
    float* ws  = hs + 32 * RSTR;        // 8*516
    float* mus = ws + 8 * RSTR;         // 512
    float* rss = mus + 512;             // 512
    float* lg  = rss + 512;             // 256
    __shared__ float susage[EE];
    int tid = threadIdx.x;
    int t0 = blockIdx.x * 32;

    if (tid < EE) susage[tid] = 0.f;
    for (int c = tid; c < CC; c += 256) {
        float m = g_sum[c] * (1.0f / TT);
        float v = g_sumsq[c] * (1.0f / TT) - m * m;
        mus[c] = m;
        rss[c] = rsqrtf(v + 1e-5f);
    }
    for (int i = tid; i < EE * CC; i += 256) {
        int e = i >> 9, c = i & 511;
        ws[e * RSTR + c] = wg2[i];
    }
    __syncthreads();
#pragma unroll
    for (int it = 0; it < 16; it++) {
        int idx = tid + it * 256;
        int t = idx >> 7, c = (idx & 127) << 2;
        float4 v = *(const float4*)(g_h + (size_t)(t0 + t) * CC + c);
        float4 o;
        o.x = fmaxf(gamma[c + 0] * (v.x - mus[c + 0]) * rss[c + 0] + beta[c + 0], 0.f);
        o.y = fmaxf(gamma[c + 1] * (v.y - mus[c + 1]) * rss[c + 1] + beta[c + 1], 0.f);
        o.z = fmaxf(gamma[c + 2] * (v.z - mus[c + 2]) * rss[c + 2] + beta[c + 2], 0.f);
        o.w = fmaxf(gamma[c + 3] * (v.w - mus[c + 3]) * rss[c + 3] + beta[c + 3], 0.f);
        *(float4*)(hs + t * RSTR + c) = o;
    }
    __syncthreads();
    {
        int t = tid >> 3, e = tid & 7;
        const float4* hp = (const float4*)(hs + t * RSTR);
        const float4* wp = (const float4*)(ws + e * RSTR);
        float acc = 0.f;
#pragma unroll 8
        for (int i = 0; i < 128; i++) {
            float4 a = hp[i], b = wp[i];
            acc += a.x * b.x + a.y * b.y + a.z * b.z + a.w * b.w;
        }
        lg[t * 8 + e] = acc + bg2[e];
    }
    __syncthreads();
    if (tid < 32) {
        int t = t0 + tid;
        float l[EE];
#pragma unroll
        for (int e = 0; e < EE; e++) l[e] = lg[tid * 8 + e];
        int e0 = 0; float v0 = l[0];
#pragma unroll
        for (int e = 1; e < EE; e++) if (l[e] > v0) { v0 = l[e]; e0 = e; }
        int e1 = -1; float v1 = -1e30f;
#pragma unroll
        for (int e = 0; e < EE; e++) if (e != e0 && l[e] > v1) { v1 = l[e]; e1 = e; }
        float v2 = -1e30f;
#pragma unroll
        for (int e = 0; e < EE; e++) if (e != e0 && e != e1 && l[e] > v2) v2 = l[e];
        float ex = expf(v1 - v0);
        float inv = 1.f / (1.f + ex);
        g_re[t * 2] = e0; g_re[t * 2 + 1] = e1;
        g_rw[t * 2] = inv; g_rw[t * 2 + 1] = ex * inv;
        bool flagged = (v1 - v2) < 1e-3f;
        if (flagged) {
            int pos = atomicAdd(&g_nfix, 1);
            if (pos < FIXCAP) g_fix[pos] = t; else flagged = false;
        }
        if (!flagged) {
            atomicAdd(&susage[e0], inv);
            atomicAdd(&susage[e1], ex * inv);
        }
    }
    __syncthreads();
    if (tid < EE) atomicAdd(&g_usage[tid], susage[tid]);
}

// ---------------- exact fp32 recompute for near-tie tokens -------------------
__global__ __launch_bounds__(256) void k_fix(const float* __restrict__ x,
                                             const float* __restrict__ wg1,
                                             const float* __restrict__ gamma,
                                             const float* __restrict__ beta,
                                             const float* __restrict__ wg2,
                                             const float* __restrict__ bg2) {
    __shared__ float xr[CC], rr[CC], lg[EE];
    int tid = threadIdx.x, w = tid >> 5, ln = tid & 31;
    int nf = g_nfix; if (nf > FIXCAP) nf = FIXCAP;
    for (int fi = blockIdx.x; fi < nf; fi += gridDim.x) {
        int t = g_fix[fi];
        __syncthreads();
        xr[tid] = x[(size_t)t * CC + tid];
        xr[tid + 256] = x[(size_t)t * CC + tid + 256];
        __syncthreads();
        for (int c = w; c < CC; c += 8) {
            const float* wr = wg1 + (size_t)c * CC;
            float a = 0.f;
#pragma unroll
            for (int j = 0; j < 16; j++) { int k = j * 32 + ln; a += xr[k] * wr[k]; }
#pragma unroll
            for (int off = 16; off; off >>= 1) a += __shfl_xor_sync(0xffffffffu, a, off);
            if (ln == 0) {
                float mu = g_sum[c] * (1.0f / TT);
                float var = g_sumsq[c] * (1.0f / TT) - mu * mu;
                rr[c] = fmaxf(gamma[c] * (a - mu) * rsqrtf(var + 1e-5f) + beta[c], 0.f);
            }
        }
        __syncthreads();
        if (w < EE) {
            const float* we = wg2 + w * CC;
            float a = 0.f;
#pragma unroll
            for (int j = 0; j < 16; j++) { int k = j * 32 + ln; a += rr[k] * we[k]; }
#pragma unroll
            for (int off = 16; off; off >>= 1) a += __shfl_xor_sync(0xffffffffu, a, off);
            if (ln == 0) lg[w] = a + bg2[w];
        }
        __syncthreads();
        if (tid == 0) {
            int e0 = 0; float v0 = lg[0];
#pragma unroll
            for (int e = 1; e < EE; e++) if (lg[e] > v0) { v0 = lg[e]; e0 = e; }
            int e1 = -1; float v1 = -1e30f;
#pragma unroll
            for (int e = 0; e < EE; e++) if (e != e0 && lg[e] > v1) { v1 = lg[e]; e1 = e; }
            float ex = expf(v1 - v0);
            float inv = 1.f / (1.f + ex);
            g_re[t * 2] = e0; g_re[t * 2 + 1] = e1;
            g_rw[t * 2] = inv; g_rw[t * 2 + 1] = ex * inv;
            atomicAdd(&g_usage[e0], inv);
            atomicAdd(&g_usage[e1], ex * inv);
        }
    }
}

// ---------------- experts + weighted combine + transpose ---------------------
__global__ __launch_bounds__(256) void k_expert(const float* __restrict__ x,
                                                const float* __restrict__ w1,
                                                const float* __restrict__ b1,
                                                const float* __restrict__ w2,
                                                const float* __restrict__ b2,
                                                float* __restrict__ out) {
    extern __shared__ float dynsm[];
    float* tile = dynsm;
    float* wbuf = dynsm + 64 * TSTR;
    float* h1s  = wbuf + 8192;
    float* b2s  = h1s + 2048;

    __shared__ int cnt[EE];
    __shared__ unsigned char lst[EE][64];
    __shared__ float rw[128];

    int tid = threadIdx.x;
    int tg0 = blockIdx.x * 64;
    int bidx = tg0 >> 12;
    int n0 = tg0 & (NNN - 1);

    for (int idx = tid; idx < 64 * 128; idx += 256) {
        int t = idx >> 7;
        int c = (idx & 127) << 2;
        float4 v = *(const float4*)(x + (size_t)(tg0 + t) * CC + c);
        *(float4*)(tile + t * TSTR + c) = v;
    }
    if (tid < EE) cnt[tid] = 0;
    __syncthreads();
    if (tid < 128) {
        int t = tid >> 1, s = tid & 1;
        int e = g_re[(tg0 + t) * 2 + s];
        rw[tid] = g_rw[(tg0 + t) * 2 + s];
        int p = atomicAdd(&cnt[e], 1);
        lst[e][p] = (unsigned char)tid;
    }
    __syncthreads();

    int h = tid & 15, j = tid >> 4;
    for (int e = 0; e < EE; e++) {
        for (int idx = tid; idx < CC * HH; idx += 256) wbuf[idx] = w1[e * CC * HH + idx];
        __syncthreads();
        int m = cnt[e];
        float bb = b1[e * HH + h];
        for (int base = 0; base < m; base += 16) {
            int ii = base + j;
            if (ii < m) {
                int ts = lst[e][ii];
                int t = ts >> 1, slot = ts & 1;
                const float* xr = tile + t * TSTR;
                float acc = 0.f;
#pragma unroll 8
                for (int c = 0; c < CC; c += 4) {
                    float4 xv = *(const float4*)(xr + c);
                    acc += xv.x * wbuf[c * 16 + h];
                    acc += xv.y * wbuf[(c + 1) * 16 + h];
                    acc += xv.z * wbuf[(c + 2) * 16 + h];
                    acc += xv.w * wbuf[(c + 3) * 16 + h];
                }
                h1s[t * 32 + slot * 16 + h] = fmaxf(acc + bb, 0.f);
            }
        }
        __syncthreads();
    }

    for (int idx = tid; idx < 64 * TSTR; idx += 256) tile[idx] = 0.f;
    __syncthreads();

    for (int e = 0; e < EE; e++) {
        for (int idx = tid; idx < HH * CC; idx += 256) wbuf[idx] = w2[e * HH * CC + idx];
        for (int idx = tid; idx < CC; idx += 256) b2s[idx] = b2[e * CC + idx];
        __syncthreads();
        int m = cnt[e];
        for (int ii = 0; ii < m; ii++) {
            int ts = lst[e][ii];
            int t = ts >> 1, slot = ts & 1;
            float w = rw[ts];
            const float* hh = h1s + t * 32 + slot * 16;
            float hr[16];
#pragma unroll
            for (int k = 0; k < 16; k++) hr[k] = hh[k];
            for (int c = tid; c < CC; c += 256) {
                float acc = b2s[c];
#pragma unroll
                for (int k = 0; k < 16; k++) acc += hr[k] * wbuf[k * CC + c];
                tile[t * TSTR + c] += w * acc;
            }
        }
        __syncthreads();
    }

    int t = tid & 63, c0 = tid >> 6;
    float* ob = out + (size_t)bidx * CC * NNN + n0 + t;
    for (int c = c0; c < CC; c += 4) ob[(size_t)c * NNN] = tile[t * TSTR + c];
}

// ---------------- load-balance loss -------------------------------------------
__global__ void k_lb(float* __restrict__ out, long long out_size) {
    if (threadIdx.x == 0 && out_size > (long long)BB * CC * NNN) {
        float s = 0.f;
#pragma unroll
        for (int e = 0; e < EE; e++) {
            float u = g_usage[e] * (1.0f / TT);
            s += u * u;
        }
        out[(size_t)BB * CC * NNN] = s * (float)EE;
    }
}

// ---------------- launch --------------------------------------------------------
extern "C" void kernel_launch(void* const* d_in, const int* in_sizes, int n_in,
                              void* d_out, int out_size) {
    const float* x     = (const float*)d_in[0];
    const float* wg1   = (const float*)d_in[1];
    const float* bg1   = (const float*)d_in[2];
    const float* gamma = (const float*)d_in[3];
    const float* beta  = (const float*)d_in[4];
    const float* wg2   = (const float*)d_in[5];
    const float* bg2   = (const float*)d_in[6];
    const float* w1    = (const float*)d_in[7];
    const float* b1    = (const float*)d_in[8];
    const float* w2    = (const float*)d_in[9];
    const float* b2    = (const float*)d_in[10];
    float* out = (float*)d_out;

    int smemE = (64 * TSTR + 8192 + 2048 + 512) * (int)sizeof(float);   // 175104
    int smemG = GSMEM;                                                  // 65536
    int smemR = (32 * RSTR + 8 * RSTR + 512 + 512 + 256) * (int)sizeof(float); // 87680
    cudaFuncSetAttribute(k_expert, cudaFuncAttributeMaxDynamicSharedMemorySize, smemE);
    cudaFuncSetAttribute(k_gemm,   cudaFuncAttributeMaxDynamicSharedMemorySize, smemG);
    cudaFuncSetAttribute(k_route,  cudaFuncAttributeMaxDynamicSharedMemorySize, smemR);

    k_zero<<<1, 512>>>();
    {
        long long tot4 = ((long long)TT * CC + (long long)CC * CC) / 4;
        int nb = (int)((tot4 + 255) / 256);
        k_split<<<nb, 256>>>(x, wg1);
    }
    dim3 gg(CC / 128, TT / 128);
    k_gemm<<<gg, 256, GSMEM>>>(bg1);
    k_bnstats<<<TT / 128, 512>>>();
    k_route<<<TT / 32, 256, smemR>>>(gamma, beta, wg2, bg2);
    k_fix<<<256, 256>>>(x, wg1, gamma, beta, wg2, bg2);
    k_expert<<<TT / 64, 256, smemE>>>(x, w1, b1, w2, b2, out);
    k_lb<<<1, 32>>>(out, (long long)out_size);
}

// round 4
// speedup vs baseline: 1.2256x; 1.0012x over previous
#include <cuda_runtime.h>
#include <cuda_bf16.h>
#include <math.h>
#include <stdint.h>

#define TT   32768
#define CC   512
#define EE   8
#define HH   16
#define BB   8
#define NNN  4096
#define TSTR 516
#define FIXCAP 8192

// ---------------- scratch (static device globals; no allocation) -------------
__device__ float g_h[(size_t)TT * CC];     // gate hidden, 64MB
__device__ int   g_re[TT * 2];
__device__ float g_rw[TT * 2];
__device__ float g_sum[CC];
__device__ float g_sumsq[CC];
__device__ float g_usage[EE];
__device__ int   g_nfix;
__device__ int   g_fix[FIXCAP];
__device__ __align__(16) __nv_bfloat16 g_xh[(size_t)TT * CC];
__device__ __align__(16) __nv_bfloat16 g_xl[(size_t)TT * CC];
__device__ __align__(16) __nv_bfloat16 g_wh[CC * CC];
__device__ __align__(16) __nv_bfloat16 g_wl[CC * CC];

// ---------------- PTX helpers (non-'a' target safe: ldmatrix + mma.sync) -----
__device__ __forceinline__ uint32_t smem_u32(const void* p) {
    uint32_t a;
    asm("{ .reg .u64 t; cvta.to.shared.u64 t, %1; cvt.u32.u64 %0, t; }" : "=r"(a) : "l"(p));
    return a;
}
__device__ __forceinline__ void ldm4(uint32_t* r, uint32_t a) {
    asm volatile("ldmatrix.sync.aligned.m8n8.x4.shared.b16 {%0,%1,%2,%3}, [%4];"
                 : "=r"(r[0]), "=r"(r[1]), "=r"(r[2]), "=r"(r[3]) : "r"(a));
}
__device__ __forceinline__ void mma16816(float* d, const uint32_t* a,
                                         uint32_t b0, uint32_t b1) {
    asm volatile(
        "mma.sync.aligned.m16n8k16.row.col.f32.bf16.bf16.f32 "
        "{%0,%1,%2,%3}, {%4,%5,%6,%7}, {%8,%9}, {%0,%1,%2,%3};"
        : "+f"(d[0]), "+f"(d[1]), "+f"(d[2]), "+f"(d[3])
        : "r"(a[0]), "r"(a[1]), "r"(a[2]), "r"(a[3]), "r"(b0), "r"(b1));
}

// ---------------- zero accumulators ------------------------------------------
__global__ void k_zero() {
    int i = threadIdx.x;
    if (i < CC) { g_sum[i] = 0.f; g_sumsq[i] = 0.f; }
    if (i < EE) g_usage[i] = 0.f;
    if (i == 0) g_nfix = 0;
}

// ---------------- bf16 hi/lo split of x and wg1 ------------------------------
__global__ __launch_bounds__(256) void k_split(const float* __restrict__ x,
                                               const float* __restrict__ wg1) {
    size_t i4 = (size_t)blockIdx.x * 256 + threadIdx.x;
    const size_t nx = (size_t)TT * CC / 4, nw = (size_t)CC * CC / 4;
    const float* s; __nv_bfloat16 *dh, *dl; size_t o;
    if (i4 < nx)           { s = x;   o = i4;      dh = g_xh; dl = g_xl; }
    else if (i4 < nx + nw) { s = wg1; o = i4 - nx; dh = g_wh; dl = g_wl; }
    else return;
    float4 v = ((const float4*)s)[o];
    float a[4] = {v.x, v.y, v.z, v.w};
    unsigned hh[4], ll[4];
#pragma unroll
    for (int i = 0; i < 4; i++) {
        __nv_bfloat16 hb = __float2bfloat16(a[i]);
        __nv_bfloat16 lb = __float2bfloat16(a[i] - __bfloat162float(hb));
        hh[i] = ((__nv_bfloat16_raw)hb).x;
        ll[i] = ((__nv_bfloat16_raw)lb).x;
    }
    uint2 ph = {hh[0] | (hh[1] << 16), hh[2] | (hh[3] << 16)};
    uint2 pl = {ll[0] | (ll[1] << 16), ll[2] | (ll[3] << 16)};
    ((uint2*)dh)[o] = ph;
    ((uint2*)dl)[o] = pl;
}

// ---------------- gate GEMM1 via mma.sync (HMMA): h = x @ wg1^T + bg1 --------
// 3-term bf16 split. Block tile 128x128, BK=64 (128B SW128 rows).
// 8 warps, warp tile 32x64: 2 (m16) x 8 (n8) HMMA per k16.
#define GSMEM 65536

__global__ __launch_bounds__(256, 2) void k_gemm(const float* __restrict__ bg1) {
    extern __shared__ char smc[];
    uint32_t sb = smem_u32(smc);
    int tid = threadIdx.x;
    int n0 = blockIdx.x * 128, m0 = blockIdx.y * 128;
    int warp = tid >> 5, lane = tid & 31;
    int wm = warp >> 1, wn = warp & 1;

    float acc[2][8][4];
#pragma unroll
    for (int i = 0; i < 2; i++)
#pragma unroll
        for (int j = 0; j < 8; j++)
#pragma unroll
            for (int q = 0; q < 4; q++) acc[i][j][q] = 0.f;

    // ldmatrix lane addressing
    int li = lane & 7, lm = lane >> 3;
    int a_row = (lm & 1) * 8 + li, a_cb = (lm >> 1) * 16;   // A frag order a0..a3
    int b_row = (lm >> 1) * 8 + li, b_cb = (lm & 1) * 16;   // B: two n8 tiles per x4

    const __nv_bfloat16* gp[4] = {g_xh, g_xl, g_wh, g_wl};
    const int rb[4] = {m0, m0, n0, n0};

    for (int kc = 0; kc < 8; kc++) {
        int k0 = kc * 64;
#pragma unroll
        for (int tt = 0; tt < 4; tt++) {
            const __nv_bfloat16* src = gp[tt];
            char* dst = smc + tt * 16384;
            int rbase = rb[tt];
#pragma unroll
            for (int it = 0; it < 8; it++) {
                int idx = tid + it * 256;
                int r = idx >> 4, c4 = (idx & 15) << 2;
                uint2 v = *(const uint2*)(src + (size_t)(rbase + r) * CC + k0 + c4);
                uint32_t bo = (r << 7) + (c4 << 1);
                bo ^= (bo >> 3) & 0x70;
                *(uint2*)(dst + bo) = v;
            }
        }
        __syncthreads();

        // three term pairs: (Ah,Bh), (Ah,Bl), (Al,Bh)
#pragma unroll
        for (int tp = 0; tp < 3; tp++) {
            uint32_t abase = sb + ((tp == 2) ? 16384 : 0);
            uint32_t bbase = sb + 32768 + ((tp == 1) ? 16384 : 0);
#pragma unroll
            for (int ks = 0; ks < 4; ks++) {
                int kb = ks * 32;
                uint32_t af[2][4];
#pragma unroll
                for (int mi = 0; mi < 2; mi++) {
                    int r = wm * 32 + mi * 16 + a_row;
                    uint32_t cb = (uint32_t)(kb + a_cb);
                    uint32_t addr = abase + (r << 7) + (cb ^ ((r & 7) << 4));
                    ldm4(af[mi], addr);
                }
                uint32_t bfr[4][4];
#pragma unroll
                for (int p = 0; p < 4; p++) {
                    int r = wn * 64 + p * 16 + b_row;
                    uint32_t cb = (uint32_t)(kb + b_cb);
                    uint32_t addr = bbase + (r << 7) + (cb ^ ((r & 7) << 4));
                    ldm4(bfr[p], addr);
                }
#pragma unroll
                for (int mi = 0; mi < 2; mi++)
#pragma unroll
                    for (int ni = 0; ni < 8; ni++)
                        mma16816(acc[mi][ni], af[mi],
                                 bfr[ni >> 1][(ni & 1) * 2],
                                 bfr[ni >> 1][(ni & 1) * 2 + 1]);
            }
        }
        __syncthreads();
    }

    // epilogue: h = acc + bias
    int g = lane >> 2, tg = lane & 3;
#pragma unroll
    for (int mi = 0; mi < 2; mi++) {
        int row = m0 + wm * 32 + mi * 16 + g;
#pragma unroll
        for (int ni = 0; ni < 8; ni++) {
            int col = n0 + wn * 64 + ni * 8 + tg * 2;
            float bx = bg1[col], by = bg1[col + 1];
            float2 v0 = {acc[mi][ni][0] + bx, acc[mi][ni][1] + by};
            float2 v1 = {acc[mi][ni][2] + bx, acc[mi][ni][3] + by};
            *(float2*)(g_h + (size_t)row * CC + col) = v0;
            *(float2*)(g_h + (size_t)(row + 8) * CC + col) = v1;
        }
    }
}

// ---------------- BN batch stats ---------------------------------------------
__global__ __launch_bounds__(512) void k_bnstats() {
    int c = threadIdx.x;
    int t0 = blockIdx.x * 128;
    float s = 0.f, s2 = 0.f;
    for (int t = 0; t < 128; t++) {
        float v = g_h[(size_t)(t0 + t) * CC + c];
        s += v; s2 += v * v;
    }
    atomicAdd(&g_sum[c], s);
    atomicAdd(&g_sumsq[c], s2);
}

// ---------------- BN + ReLU + gate GEMM2 + top-2 routing (tiled) -------------
#define RSTR 516
__global__ __launch_bounds__(256) void k_route(const float* __restrict__ gamma,
                                               const float* __restrict__ beta,
                                               const float* __restrict__ wg2,
                                               const float* __restrict__ bg2) {
    extern __shared__ float dynsm[];
    float* hs  = dynsm;                 // 32*516
    float* ws  = hs + 32 * RSTR;        // 8*516
    float* mus = ws + 8 * RSTR;         // 512
    float* rss = mus + 512;             // 512
    float* lg  = rss + 512;             // 256
    __shared__ float susage[EE];
    int tid = threadIdx.x;
    int t0 = blockIdx.x * 32;

    if (tid < EE) susage[tid] = 0.f;
    for (int c = tid; c < CC; c += 256) {
        float m = g_sum[c] * (1.0f / TT);
        float v = g_sumsq[c] * (1.0f / TT) - m * m;
        mus[c] = m;
        rss[c] = rsqrtf(v + 1e-5f);
    }
    for (int i = tid; i < EE * CC; i += 256) {
        int e = i >> 9, c = i & 511;
        ws[e * RSTR + c] = wg2[i];
    }
    __syncthreads();
#pragma unroll
    for (int it = 0; it < 16; it++) {
        int idx = tid + it * 256;
        int t = idx >> 7, c = (idx & 127) << 2;
        float4 v = *(const float4*)(g_h + (size_t)(t0 + t) * CC + c);
        float4 o;
        o.x = fmaxf(gamma[c + 0] * (v.x - mus[c + 0]) * rss[c + 0] + beta[c + 0], 0.f);
        o.y = fmaxf(gamma[c + 1] * (v.y - mus[c + 1]) * rss[c + 1] + beta[c + 1], 0.f);
        o.z = fmaxf(gamma[c + 2] * (v.z - mus[c + 2]) * rss[c + 2] + beta[c + 2], 0.f);
        o.w = fmaxf(gamma[c + 3] * (v.w - mus[c + 3]) * rss[c + 3] + beta[c + 3], 0.f);
        *(float4*)(hs + t * RSTR + c) = o;
    }
    __syncthreads();
    {
        int t = tid >> 3, e = tid & 7;
        const float4* hp = (const float4*)(hs + t * RSTR);
        const float4* wp = (const float4*)(ws + e * RSTR);
        float acc = 0.f;
#pragma unroll 8
        for (int i = 0; i < 128; i++) {
            float4 a = hp[i], b = wp[i];
            acc += a.x * b.x + a.y * b.y + a.z * b.z + a.w * b.w;
        }
        lg[t * 8 + e] = acc + bg2[e];
    }
    __syncthreads();
    if (tid < 32) {
        int t = t0 + tid;
        float l[EE];
#pragma unroll
        for (int e = 0; e < EE; e++) l[e] = lg[tid * 8 + e];
        int e0 = 0; float v0 = l[0];
#pragma unroll
        for (int e = 1; e < EE; e++) if (l[e] > v0) { v0 = l[e]; e0 = e; }
        int e1 = -1; float v1 = -1e30f;
#pragma unroll
        for (int e = 0; e < EE; e++) if (e != e0 && l[e] > v1) { v1 = l[e]; e1 = e; }
        float v2 = -1e30f;
#pragma unroll
        for (int e = 0; e < EE; e++) if (e != e0 && e != e1 && l[e] > v2) v2 = l[e];
        float ex = expf(v1 - v0);
        float inv = 1.f / (1.f + ex);
        g_re[t * 2] = e0; g_re[t * 2 + 1] = e1;
        g_rw[t * 2] = inv; g_rw[t * 2 + 1] = ex * inv;
        bool flagged = (v1 - v2) < 1e-3f;
        if (flagged) {
            int pos = atomicAdd(&g_nfix, 1);
            if (pos < FIXCAP) g_fix[pos] = t; else flagged = false;
        }
        if (!flagged) {
            atomicAdd(&susage[e0], inv);
            atomicAdd(&susage[e1], ex * inv);
        }
    }
    __syncthreads();
    if (tid < EE) atomicAdd(&g_usage[tid], susage[tid]);
}

// ---------------- exact fp32 recompute for near-tie tokens -------------------
__global__ __launch_bounds__(256) void k_fix(const float* __restrict__ x,
                                             const float* __restrict__ wg1,
                                             const float* __restrict__ gamma,
                                             const float* __restrict__ beta,
                                             const float* __restrict__ wg2,
                                             const float* __restrict__ bg2) {
    __shared__ float xr[CC], rr[CC], lg[EE];
    int tid = threadIdx.x, w = tid >> 5, ln = tid & 31;
    int nf = g_nfix; if (nf > FIXCAP) nf = FIXCAP;
    for (int fi = blockIdx.x; fi < nf; fi += gridDim.x) {
        int t = g_fix[fi];
        __syncthreads();
        xr[tid] = x[(size_t)t * CC + tid];
        xr[tid + 256] = x[(size_t)t * CC + tid + 256];
        __syncthreads();
        for (int c = w; c < CC; c += 8) {
            const float* wr = wg1 + (size_t)c * CC;
            float a = 0.f;
#pragma unroll
            for (int j = 0; j < 16; j++) { int k = j * 32 + ln; a += xr[k] * wr[k]; }
#pragma unroll
            for (int off = 16; off; off >>= 1) a += __shfl_xor_sync(0xffffffffu, a, off);
            if (ln == 0) {
                float mu = g_sum[c] * (1.0f / TT);
                float var = g_sumsq[c] * (1.0f / TT) - mu * mu;
                rr[c] = fmaxf(gamma[c] * (a - mu) * rsqrtf(var + 1e-5f) + beta[c], 0.f);
            }
        }
        __syncthreads();
        if (w < EE) {
            const float* we = wg2 + w * CC;
            float a = 0.f;
#pragma unroll
            for (int j = 0; j < 16; j++) { int k = j * 32 + ln; a += rr[k] * we[k]; }
#pragma unroll
            for (int off = 16; off; off >>= 1) a += __shfl_xor_sync(0xffffffffu, a, off);
            if (ln == 0) lg[w] = a + bg2[w];
        }
        __syncthreads();
        if (tid == 0) {
            int e0 = 0; float v0 = lg[0];
#pragma unroll
            for (int e = 1; e < EE; e++) if (lg[e] > v0) { v0 = lg[e]; e0 = e; }
            int e1 = -1; float v1 = -1e30f;
#pragma unroll
            for (int e = 0; e < EE; e++) if (e != e0 && lg[e] > v1) { v1 = lg[e]; e1 = e; }
            float ex = expf(v1 - v0);
            float inv = 1.f / (1.f + ex);
            g_re[t * 2] = e0; g_re[t * 2 + 1] = e1;
            g_rw[t * 2] = inv; g_rw[t * 2 + 1] = ex * inv;
            atomicAdd(&g_usage[e0], inv);
            atomicAdd(&g_usage[e1], ex * inv);
        }
    }
}

// ---------------- experts + weighted combine + transpose ---------------------
__global__ __launch_bounds__(256) void k_expert(const float* __restrict__ x,
                                                const float* __restrict__ w1,
                                                const float* __restrict__ b1,
                                                const float* __restrict__ w2,
                                                const float* __restrict__ b2,
                                                float* __restrict__ out) {
    extern __shared__ float dynsm[];
    float* tile = dynsm;
    float* wbuf = dynsm + 64 * TSTR;
    float* h1s  = wbuf + 8192;
    float* b2s  = h1s + 2048;

    __shared__ int cnt[EE];
    __shared__ unsigned char lst[EE][64];
    __shared__ float rw[128];

    int tid = threadIdx.x;
    int tg0 = blockIdx.x * 64;
    int bidx = tg0 >> 12;
    int n0 = tg0 & (NNN - 1);

    for (int idx = tid; idx < 64 * 128; idx += 256) {
        int t = idx >> 7;
        int c = (idx & 127) << 2;
        float4 v = *(const float4*)(x + (size_t)(tg0 + t) * CC + c);
        *(float4*)(tile + t * TSTR + c) = v;
    }
    if (tid < EE) cnt[tid] = 0;
    __syncthreads();
    if (tid < 128) {
        int t = tid >> 1, s = tid & 1;
        int e = g_re[(tg0 + t) * 2 + s];
        rw[tid] = g_rw[(tg0 + t) * 2 + s];
        int p = atomicAdd(&cnt[e], 1);
        lst[e][p] = (unsigned char)tid;
    }
    __syncthreads();

    int h = tid & 15, j = tid >> 4;
    for (int e = 0; e < EE; e++) {
        for (int idx = tid; idx < CC * HH; idx += 256) wbuf[idx] = w1[e * CC * HH + idx];
        __syncthreads();
        int m = cnt[e];
        float bb = b1[e * HH + h];
        for (int base = 0; base < m; base += 16) {
            int ii = base + j;
            if (ii < m) {
                int ts = lst[e][ii];
                int t = ts >> 1, slot = ts & 1;
                const float* xr = tile + t * TSTR;
                float acc = 0.f;
#pragma unroll 8
                for (int c = 0; c < CC; c += 4) {
                    float4 xv = *(const float4*)(xr + c);
                    acc += xv.x * wbuf[c * 16 + h];
                    acc += xv.y * wbuf[(c + 1) * 16 + h];
                    acc += xv.z * wbuf[(c + 2) * 16 + h];
                    acc += xv.w * wbuf[(c + 3) * 16 + h];
                }
                h1s[t * 32 + slot * 16 + h] = fmaxf(acc + bb, 0.f);
            }
        }
        __syncthreads();
    }

    for (int idx = tid; idx < 64 * TSTR; idx += 256) tile[idx] = 0.f;
    __syncthreads();

    for (int e = 0; e < EE; e++) {
        for (int idx = tid; idx < HH * CC; idx += 256) wbuf[idx] = w2[e * HH * CC + idx];
        for (int idx = tid; idx < CC; idx += 256) b2s[idx] = b2[e * CC + idx];
        __syncthreads();
        int m = cnt[e];
        for (int ii = 0; ii < m; ii++) {
            int ts = lst[e][ii];
            int t = ts >> 1, slot = ts & 1;
            float w = rw[ts];
            const float* hh = h1s + t * 32 + slot * 16;
            float hr[16];
#pragma unroll
            for (int k = 0; k < 16; k++) hr[k] = hh[k];
            for (int c = tid; c < CC; c += 256) {
                float acc = b2s[c];
#pragma unroll
                for (int k = 0; k < 16; k++) acc += hr[k] * wbuf[k * CC + c];
                tile[t * TSTR + c] += w * acc;
            }
        }
        __syncthreads();
    }

    int t = tid & 63, c0 = tid >> 6;
    float* ob = out + (size_t)bidx * CC * NNN + n0 + t;
    for (int c = c0; c < CC; c += 4) ob[(size_t)c * NNN] = tile[t * TSTR + c];
}

// ---------------- load-balance loss -------------------------------------------
__global__ void k_lb(float* __restrict__ out, long long out_size) {
    if (threadIdx.x == 0 && out_size > (long long)BB * CC * NNN) {
        float s = 0.f;
#pragma unroll
        for (int e = 0; e < EE; e++) {
            float u = g_usage[e] * (1.0f / TT);
            s += u * u;
        }
        out[(size_t)BB * CC * NNN] = s * (float)EE;
    }
}

// ---------------- launch --------------------------------------------------------
extern "C" void kernel_launch(void* const* d_in, const int* in_sizes, int n_in,
                              void* d_out, int out_size) {
    const float* x     = (const float*)d_in[0];
    const float* wg1   = (const float*)d_in[1];
    const float* bg1   = (const float*)d_in[2];
    const float* gamma = (const float*)d_in[3];
    const float* beta  = (const float*)d_in[4];
    const float* wg2   = (const float*)d_in[5];
    const float* bg2   = (const float*)d_in[6];
    const float* w1    = (const float*)d_in[7];
    const float* b1    = (const float*)d_in[8];
    const float* w2    = (const float*)d_in[9];
    const float* b2    = (const float*)d_in[10];
    float* out = (float*)d_out;

    int smemE = (64 * TSTR + 8192 + 2048 + 512) * (int)sizeof(float);   // 175104
    int smemG = GSMEM;                                                  // 65536
    int smemR = (32 * RSTR + 8 * RSTR + 512 + 512 + 256) * (int)sizeof(float); // 87680
    cudaFuncSetAttribute(k_expert, cudaFuncAttributeMaxDynamicSharedMemorySize, smemE);
    cudaFuncSetAttribute(k_gemm,   cudaFuncAttributeMaxDynamicSharedMemorySize, smemG);
    cudaFuncSetAttribute(k_route,  cudaFuncAttributeMaxDynamicSharedMemorySize, smemR);

    k_zero<<<1, 512>>>();
    {
        long long tot4 = ((long long)TT * CC + (long long)CC * CC) / 4;
        int nb = (int)((tot4 + 255) / 256);
        k_split<<<nb, 256>>>(x, wg1);
    }
    dim3 gg(CC / 128, TT / 128);
    k_gemm<<<gg, 256, GSMEM>>>(bg1);
    k_bnstats<<<TT / 128, 512>>>();
    k_route<<<TT / 32, 256, smemR>>>(gamma, beta, wg2, bg2);
    k_fix<<<256, 256>>>(x, wg1, gamma, beta, wg2, bg2);
    k_expert<<<TT / 64, 256, smemE>>>(x, w1, b1, w2, b2, out);
    k_lb<<<1, 32>>>(out, (long long)out_size);
}

// round 5
// speedup vs baseline: 1.5666x; 1.2782x over previous
#include <cuda_runtime.h>
#include <cuda_bf16.h>
#include <math.h>
#include <stdint.h>

#define TT   32768
#define CC   512
#define EE   8
#define HH   16
#define BB   8
#define NNN  4096
#define TSTR 516
#define FIXCAP 8192

// ---------------- scratch (static device globals; no allocation) -------------
__device__ float g_h[(size_t)TT * CC];     // gate hidden, 64MB
__device__ int   g_re[TT * 2];
__device__ float g_rw[TT * 2];
__device__ float g_sum[CC];
__device__ float g_sumsq[CC];
__device__ float g_usage[EE];
__device__ int   g_nfix;
__device__ int   g_fix[FIXCAP];
__device__ __align__(16) __nv_bfloat16 g_xh[(size_t)TT * CC];
__device__ __align__(16) __nv_bfloat16 g_wh[CC * CC];
__device__ __align__(16) __nv_bfloat16 g_wl[CC * CC];

// ---------------- PTX helpers -------------------------------------------------
__device__ __forceinline__ uint32_t smem_u32(const void* p) {
    uint32_t a;
    asm("{ .reg .u64 t; cvta.to.shared.u64 t, %1; cvt.u32.u64 %0, t; }" : "=r"(a) : "l"(p));
    return a;
}
__device__ __forceinline__ void ldm4(uint32_t* r, uint32_t a) {
    asm volatile("ldmatrix.sync.aligned.m8n8.x4.shared.b16 {%0,%1,%2,%3}, [%4];"
                 : "=r"(r[0]), "=r"(r[1]), "=r"(r[2]), "=r"(r[3]) : "r"(a));
}
__device__ __forceinline__ void mma16816(float* d, const uint32_t* a,
                                         uint32_t b0, uint32_t b1) {
    asm volatile(
        "mma.sync.aligned.m16n8k16.row.col.f32.bf16.bf16.f32 "
        "{%0,%1,%2,%3}, {%4,%5,%6,%7}, {%8,%9}, {%0,%1,%2,%3};"
        : "+f"(d[0]), "+f"(d[1]), "+f"(d[2]), "+f"(d[3])
        : "r"(a[0]), "r"(a[1]), "r"(a[2]), "r"(a[3]), "r"(b0), "r"(b1));
}
#define CP16(dst, src) asm volatile("cp.async.cg.shared.global [%0], [%1], 16;" ::"r"(dst), "l"(src) : "memory")
#define CPCOMMIT()     asm volatile("cp.async.commit_group;" ::: "memory")
#define CPWAIT(n)      asm volatile("cp.async.wait_group %0;" ::"n"(n) : "memory")

// ---------------- zero accumulators ------------------------------------------
__global__ void k_zero() {
    int i = threadIdx.x;
    if (i < CC) { g_sum[i] = 0.f; g_sumsq[i] = 0.f; }
    if (i < EE) g_usage[i] = 0.f;
    if (i == 0) g_nfix = 0;
}

// ---------------- bf16 split: xh = bf16(x); wg1 -> wh + wl -------------------
__global__ __launch_bounds__(256) void k_split(const float* __restrict__ x,
                                               const float* __restrict__ wg1) {
    size_t i4 = (size_t)blockIdx.x * 256 + threadIdx.x;
    const size_t nx = (size_t)TT * CC / 4, nw = (size_t)CC * CC / 4;
    if (i4 < nx) {
        float4 v = ((const float4*)x)[i4];
        unsigned hh[4];
        float a[4] = {v.x, v.y, v.z, v.w};
#pragma unroll
        for (int i = 0; i < 4; i++) hh[i] = ((__nv_bfloat16_raw)__float2bfloat16(a[i])).x;
        uint2 ph = {hh[0] | (hh[1] << 16), hh[2] | (hh[3] << 16)};
        ((uint2*)g_xh)[i4] = ph;
    } else if (i4 < nx + nw) {
        size_t o = i4 - nx;
        float4 v = ((const float4*)wg1)[o];
        float a[4] = {v.x, v.y, v.z, v.w};
        unsigned hh[4], ll[4];
#pragma unroll
        for (int i = 0; i < 4; i++) {
            __nv_bfloat16 hb = __float2bfloat16(a[i]);
            __nv_bfloat16 lb = __float2bfloat16(a[i] - __bfloat162float(hb));
            hh[i] = ((__nv_bfloat16_raw)hb).x;
            ll[i] = ((__nv_bfloat16_raw)lb).x;
        }
        uint2 ph = {hh[0] | (hh[1] << 16), hh[2] | (hh[3] << 16)};
        uint2 pl = {ll[0] | (ll[1] << 16), ll[2] | (ll[3] << 16)};
        ((uint2*)g_wh)[o] = ph;
        ((uint2*)g_wl)[o] = pl;
    }
}

// ---------------- gate GEMM1 (HMMA, 2-term, cp.async 2-stage) -----------------
// h = xh @ (wh+wl)^T + bg1; also accumulates BN column sums/sumsq.
// Tile 128x128, BK=64 (128B SW128 rows). Stage = Ah|Bh|Bl = 48KB. 2 stages.
#define STG 49152
#define GSMEM (2 * STG)

__global__ __launch_bounds__(256, 2) void k_gemm(const float* __restrict__ bg1) {
    extern __shared__ char smc[];
    uint32_t sb = smem_u32(smc);
    int tid = threadIdx.x;
    int n0 = blockIdx.x * 128, m0 = blockIdx.y * 128;
    int warp = tid >> 5, lane = tid & 31;
    int wm = warp >> 1, wn = warp & 1;

    const __nv_bfloat16* xs  = g_xh + (size_t)m0 * CC;
    const __nv_bfloat16* whs = g_wh + (size_t)n0 * CC;
    const __nv_bfloat16* wls = g_wl + (size_t)n0 * CC;

    float acc[2][8][4];
#pragma unroll
    for (int i = 0; i < 2; i++)
#pragma unroll
        for (int j = 0; j < 8; j++)
#pragma unroll
            for (int q = 0; q < 4; q++) acc[i][j][q] = 0.f;

    int li = lane & 7, lm = lane >> 3;
    int a_row = (lm & 1) * 8 + li, a_cb = (lm >> 1) * 16;
    int b_row = (lm >> 1) * 8 + li, b_cb = (lm & 1) * 16;

    // ---- stage loader (cp.async) ----
#define LOADSTAGE(S, K0) do {                                                   \
        uint32_t sbs = sb + (S) * STG;                                          \
        const __nv_bfloat16* srcs[3] = {xs, whs, wls};                          \
        _Pragma("unroll")                                                       \
        for (int tt = 0; tt < 3; tt++) {                                        \
            const __nv_bfloat16* src = srcs[tt];                                \
            _Pragma("unroll")                                                   \
            for (int it = 0; it < 4; it++) {                                    \
                int idx = tid + it * 256;                                       \
                int r = idx >> 3, c16 = idx & 7;                                \
                const void* g = src + (size_t)r * CC + (K0) + c16 * 8;          \
                uint32_t bo = (uint32_t)((r << 7) | (c16 << 4));                \
                bo ^= (bo >> 3) & 0x70;                                         \
                CP16(sbs + tt * 16384 + bo, g);                                 \
            }                                                                   \
        }                                                                       \
    } while (0)

    LOADSTAGE(0, 0);
    CPCOMMIT();

    for (int kc = 0; kc < 8; kc++) {
        int s = kc & 1;
        if (kc < 7) {
            LOADSTAGE(s ^ 1, (kc + 1) * 64);
            CPCOMMIT();
            CPWAIT(1);
        } else {
            CPWAIT(0);
        }
        __syncthreads();

        uint32_t abase = sb + s * STG;
#pragma unroll
        for (int tp = 0; tp < 2; tp++) {
            uint32_t bbase = abase + 16384 + tp * 16384;
#pragma unroll
            for (int ks = 0; ks < 4; ks++) {
                int kb = ks * 32;
                uint32_t af[2][4];
#pragma unroll
                for (int mi = 0; mi < 2; mi++) {
                    int r = wm * 32 + mi * 16 + a_row;
                    uint32_t cb = (uint32_t)(kb + a_cb);
                    ldm4(af[mi], abase + (r << 7) + (cb ^ ((r & 7) << 4)));
                }
                uint32_t bfr[4][4];
#pragma unroll
                for (int p = 0; p < 4; p++) {
                    int r = wn * 64 + p * 16 + b_row;
                    uint32_t cb = (uint32_t)(kb + b_cb);
                    ldm4(bfr[p], bbase + (r << 7) + (cb ^ ((r & 7) << 4)));
                }
#pragma unroll
                for (int mi = 0; mi < 2; mi++)
#pragma unroll
                    for (int ni = 0; ni < 8; ni++)
                        mma16816(acc[mi][ni], af[mi],
                                 bfr[ni >> 1][(ni & 1) * 2],
                                 bfr[ni >> 1][(ni & 1) * 2 + 1]);
            }
        }
        __syncthreads();
    }
#undef LOADSTAGE

    // ---- epilogue: bias add, store h, BN partial stats ----
    int g = lane >> 2, tg = lane & 3;
#pragma unroll
    for (int mi = 0; mi < 2; mi++) {
        int row = m0 + wm * 32 + mi * 16 + g;
#pragma unroll
        for (int ni = 0; ni < 8; ni++) {
            int col = n0 + wn * 64 + ni * 8 + tg * 2;
            float bx = bg1[col], by = bg1[col + 1];
            acc[mi][ni][0] += bx; acc[mi][ni][1] += by;
            acc[mi][ni][2] += bx; acc[mi][ni][3] += by;
            float2 v0 = {acc[mi][ni][0], acc[mi][ni][1]};
            float2 v1 = {acc[mi][ni][2], acc[mi][ni][3]};
            *(float2*)(g_h + (size_t)row * CC + col) = v0;
            *(float2*)(g_h + (size_t)(row + 8) * CC + col) = v1;
        }
    }

    float* ssum = (float*)smc;
    float* ssq  = (float*)(smc + 512);
    if (tid < 128) { ssum[tid] = 0.f; ssq[tid] = 0.f; }
    __syncthreads();
#pragma unroll
    for (int ni = 0; ni < 8; ni++) {
        int colr = wn * 64 + ni * 8 + tg * 2;
        float s0 = 0.f, s1 = 0.f, q0 = 0.f, q1 = 0.f;
#pragma unroll
        for (int mi = 0; mi < 2; mi++) {
            float a0 = acc[mi][ni][0], a1 = acc[mi][ni][1];
            float a2 = acc[mi][ni][2], a3 = acc[mi][ni][3];
            s0 += a0 + a2; s1 += a1 + a3;
            q0 += a0 * a0 + a2 * a2; q1 += a1 * a1 + a3 * a3;
        }
#pragma unroll
        for (int off = 4; off < 32; off <<= 1) {
            s0 += __shfl_xor_sync(0xffffffffu, s0, off);
            s1 += __shfl_xor_sync(0xffffffffu, s1, off);
            q0 += __shfl_xor_sync(0xffffffffu, q0, off);
            q1 += __shfl_xor_sync(0xffffffffu, q1, off);
        }
        if (g == 0) {
            atomicAdd(&ssum[colr], s0); atomicAdd(&ssum[colr + 1], s1);
            atomicAdd(&ssq[colr], q0);  atomicAdd(&ssq[colr + 1], q1);
        }
    }
    __syncthreads();
    if (tid < 128) {
        atomicAdd(&g_sum[n0 + tid], ssum[tid]);
        atomicAdd(&g_sumsq[n0 + tid], ssq[tid]);
    }
}

// ---------------- BN + ReLU + gate GEMM2 + top-2 routing (tiled) -------------
#define RSTR 516
__global__ __launch_bounds__(256) void k_route(const float* __restrict__ gamma,
                                               const float* __restrict__ beta,
                                               const float* __restrict__ wg2,
                                               const float* __restrict__ bg2) {
    extern __shared__ float dynsm[];
    float* hs  = dynsm;
    float* ws  = hs + 32 * RSTR;
    float* mus = ws + 8 * RSTR;
    float* rss = mus + 512;
    float* lg  = rss + 512;
    __shared__ float susage[EE];
    int tid = threadIdx.x;
    int t0 = blockIdx.x * 32;

    if (tid < EE) susage[tid] = 0.f;
    for (int c = tid; c < CC; c += 256) {
        float m = g_sum[c] * (1.0f / TT);
        float v = g_sumsq[c] * (1.0f / TT) - m * m;
        mus[c] = m;
        rss[c] = rsqrtf(v + 1e-5f);
    }
    for (int i = tid; i < EE * CC; i += 256) {
        int e = i >> 9, c = i & 511;
        ws[e * RSTR + c] = wg2[i];
    }
    __syncthreads();
#pragma unroll
    for (int it = 0; it < 16; it++) {
        int idx = tid + it * 256;
        int t = idx >> 7, c = (idx & 127) << 2;
        float4 v = *(const float4*)(g_h + (size_t)(t0 + t) * CC + c);
        float4 o;
        o.x = fmaxf(gamma[c + 0] * (v.x - mus[c + 0]) * rss[c + 0] + beta[c + 0], 0.f);
        o.y = fmaxf(gamma[c + 1] * (v.y - mus[c + 1]) * rss[c + 1] + beta[c + 1], 0.f);
        o.z = fmaxf(gamma[c + 2] * (v.z - mus[c + 2]) * rss[c + 2] + beta[c + 2], 0.f);
        o.w = fmaxf(gamma[c + 3] * (v.w - mus[c + 3]) * rss[c + 3] + beta[c + 3], 0.f);
        *(float4*)(hs + t * RSTR + c) = o;
    }
    __syncthreads();
    {
        int t = tid >> 3, e = tid & 7;
        const float4* hp = (const float4*)(hs + t * RSTR);
        const float4* wp = (const float4*)(ws + e * RSTR);
        float acc = 0.f;
#pragma unroll 8
        for (int i = 0; i < 128; i++) {
            float4 a = hp[i], b = wp[i];
            acc += a.x * b.x + a.y * b.y + a.z * b.z + a.w * b.w;
        }
        lg[t * 8 + e] = acc + bg2[e];
    }
    __syncthreads();
    if (tid < 32) {
        int t = t0 + tid;
        float l[EE];
#pragma unroll
        for (int e = 0; e < EE; e++) l[e] = lg[tid * 8 + e];
        int e0 = 0; float v0 = l[0];
#pragma unroll
        for (int e = 1; e < EE; e++) if (l[e] > v0) { v0 = l[e]; e0 = e; }
        int e1 = -1; float v1 = -1e30f;
#pragma unroll
        for (int e = 0; e < EE; e++) if (e != e0 && l[e] > v1) { v1 = l[e]; e1 = e; }
        float v2 = -1e30f;
#pragma unroll
        for (int e = 0; e < EE; e++) if (e != e0 && e != e1 && l[e] > v2) v2 = l[e];
        float ex = expf(v1 - v0);
        float inv = 1.f / (1.f + ex);
        g_re[t * 2] = e0; g_re[t * 2 + 1] = e1;
        g_rw[t * 2] = inv; g_rw[t * 2 + 1] = ex * inv;
        bool flagged = (v1 - v2) < 4e-3f;
        if (flagged) {
            int pos = atomicAdd(&g_nfix, 1);
            if (pos < FIXCAP) g_fix[pos] = t; else flagged = false;
        }
        if (!flagged) {
            atomicAdd(&susage[e0], inv);
            atomicAdd(&susage[e1], ex * inv);
        }
    }
    __syncthreads();
    if (tid < EE) atomicAdd(&g_usage[tid], susage[tid]);
}

// ---------------- exact fp32 recompute for near-tie tokens -------------------
__global__ __launch_bounds__(256) void k_fix(const float* __restrict__ x,
                                             const float* __restrict__ wg1,
                                             const float* __restrict__ gamma,
                                             const float* __restrict__ beta,
                                             const float* __restrict__ wg2,
                                             const float* __restrict__ bg2) {
    __shared__ float xr[CC], rr[CC], lg[EE];
    int tid = threadIdx.x, w = tid >> 5, ln = tid & 31;
    int nf = g_nfix; if (nf > FIXCAP) nf = FIXCAP;
    for (int fi = blockIdx.x; fi < nf; fi += gridDim.x) {
        int t = g_fix[fi];
        __syncthreads();
        xr[tid] = x[(size_t)t * CC + tid];
        xr[tid + 256] = x[(size_t)t * CC + tid + 256];
        __syncthreads();
        for (int c = w; c < CC; c += 8) {
            const float* wr = wg1 + (size_t)c * CC;
            float a = 0.f;
#pragma unroll
            for (int j = 0; j < 16; j++) { int k = j * 32 + ln; a += xr[k] * wr[k]; }
#pragma unroll
            for (int off = 16; off; off >>= 1) a += __shfl_xor_sync(0xffffffffu, a, off);
            if (ln == 0) {
                float mu = g_sum[c] * (1.0f / TT);
                float var = g_sumsq[c] * (1.0f / TT) - mu * mu;
                rr[c] = fmaxf(gamma[c] * (a - mu) * rsqrtf(var + 1e-5f) + beta[c], 0.f);
            }
        }
        __syncthreads();
        if (w < EE) {
            const float* we = wg2 + w * CC;
            float a = 0.f;
#pragma unroll
            for (int j = 0; j < 16; j++) { int k = j * 32 + ln; a += rr[k] * we[k]; }
#pragma unroll
            for (int off = 16; off; off >>= 1) a += __shfl_xor_sync(0xffffffffu, a, off);
            if (ln == 0) lg[w] = a + bg2[w];
        }
        __syncthreads();
        if (tid == 0) {
            int e0 = 0; float v0 = lg[0];
#pragma unroll
            for (int e = 1; e < EE; e++) if (lg[e] > v0) { v0 = lg[e]; e0 = e; }
            int e1 = -1; float v1 = -1e30f;
#pragma unroll
            for (int e = 0; e < EE; e++) if (e != e0 && lg[e] > v1) { v1 = lg[e]; e1 = e; }
            float ex = expf(v1 - v0);
            float inv = 1.f / (1.f + ex);
            g_re[t * 2] = e0; g_re[t * 2 + 1] = e1;
            g_rw[t * 2] = inv; g_rw[t * 2 + 1] = ex * inv;
            atomicAdd(&g_usage[e0], inv);
            atomicAdd(&g_usage[e1], ex * inv);
        }
    }
}

// ---------------- experts + weighted combine + transpose ---------------------
// smem: tile 64*516 | wbuf 16*532 (w1^T) | h1s 64*32
#define WSTR 532
__global__ __launch_bounds__(256) void k_expert(const float* __restrict__ x,
                                                const float* __restrict__ w1,
                                                const float* __restrict__ b1,
                                                const float* __restrict__ w2,
                                                const float* __restrict__ b2,
                                                float* __restrict__ out) {
    extern __shared__ float dynsm[];
    float* tile = dynsm;                     // 33024
    float* wbuf = dynsm + 64 * TSTR;         // 8512
    float* h1s  = wbuf + HH * WSTR;          // 2048

    __shared__ int cnt[EE];
    __shared__ unsigned char lst[EE][64];
    __shared__ float rw[128];

    int tid = threadIdx.x;
    int tg0 = blockIdx.x * 64;
    int bidx = tg0 >> 12;
    int n0 = tg0 & (NNN - 1);

    // phase A: stage x tile, build routing lists
    for (int idx = tid; idx < 64 * 128; idx += 256) {
        int t = idx >> 7;
        int c = (idx & 127) << 2;
        float4 v = *(const float4*)(x + (size_t)(tg0 + t) * CC + c);
        *(float4*)(tile + t * TSTR + c) = v;
    }
    if (tid < EE) cnt[tid] = 0;
    __syncthreads();
    if (tid < 128) {
        int t = tid >> 1, s = tid & 1;
        int e = g_re[(tg0 + t) * 2 + s];
        rw[tid] = g_rw[(tg0 + t) * 2 + s];
        int p = atomicAdd(&cnt[e], 1);
        lst[e][p] = (unsigned char)tid;
    }
    __syncthreads();

    // phase B: h1 = relu(x @ w1[e] + b1[e]); w1 transposed into wbuf[h][c]
    int h = tid & 15, j = tid >> 4;
    for (int e = 0; e < EE; e++) {
        for (int i4 = tid; i4 < 2048; i4 += 256) {
            int c = i4 >> 2, h4 = (i4 & 3) << 2;
            float4 v = *(const float4*)(w1 + (size_t)e * CC * HH + c * HH + h4);
            wbuf[(h4 + 0) * WSTR + c] = v.x;
            wbuf[(h4 + 1) * WSTR + c] = v.y;
            wbuf[(h4 + 2) * WSTR + c] = v.z;
            wbuf[(h4 + 3) * WSTR + c] = v.w;
        }
        __syncthreads();
        int m = cnt[e];
        float bb = b1[e * HH + h];
        const float* wr = wbuf + h * WSTR;
        for (int base = 0; base < m; base += 16) {
            int ii = base + j;
            if (ii < m) {
                int ts = lst[e][ii];
                int t = ts >> 1, slot = ts & 1;
                const float* xr = tile + t * TSTR;
                float acc = 0.f;
#pragma unroll 8
                for (int c = 0; c < CC; c += 4) {
                    float4 xv = *(const float4*)(xr + c);
                    float4 wv = *(const float4*)(wr + c);
                    acc += xv.x * wv.x + xv.y * wv.y + xv.z * wv.z + xv.w * wv.w;
                }
                h1s[t * 32 + slot * 16 + h] = fmaxf(acc + bb, 0.f);
            }
        }
        __syncthreads();
    }

    // reuse tile as out accumulator
    for (int idx = tid; idx < 64 * TSTR; idx += 256) tile[idx] = 0.f;
    __syncthreads();

    // phase C: out[t] += w * (h1 @ w2[e] + b2[e]); w2 in registers, 8-token batches
    {
        int c0 = tid;  // channels c0 and c0+256
        for (int e = 0; e < EE; e++) {
            int m = cnt[e];
            if (m == 0) continue;
            float wA[16], wB[16];
            const float* w2e = w2 + (size_t)e * HH * CC;
#pragma unroll
            for (int k = 0; k < 16; k++) {
                wA[k] = w2e[k * CC + c0];
                wB[k] = w2e[k * CC + c0 + 256];
            }
            float bA = b2[e * CC + c0], bB = b2[e * CC + c0 + 256];
            for (int base = 0; base < m; base += 8) {
                int ho[8], trow[8];
                float wt[8];
#pragma unroll
                for (int j2 = 0; j2 < 8; j2++) {
                    int idx2 = base + j2;
                    int ok = idx2 < m;
                    int ts = lst[e][ok ? idx2 : base];
                    trow[j2] = ts >> 1;
                    ho[j2] = (ts >> 1) * 32 + (ts & 1) * 16;
                    wt[j2] = ok ? rw[ts] : 0.f;
                }
                float a0[8], a1[8];
#pragma unroll
                for (int j2 = 0; j2 < 8; j2++) { a0[j2] = 0.f; a1[j2] = 0.f; }
#pragma unroll
                for (int k = 0; k < 16; k++) {
#pragma unroll
                    for (int j2 = 0; j2 < 8; j2++) {
                        float hv = h1s[ho[j2] + k];
                        a0[j2] += hv * wA[k];
                        a1[j2] += hv * wB[k];
                    }
                }
#pragma unroll
                for (int j2 = 0; j2 < 8; j2++) {
                    float* tr = tile + trow[j2] * TSTR;
                    tr[c0]       += wt[j2] * (a0[j2] + bA);
                    tr[c0 + 256] += wt[j2] * (a1[j2] + bB);
                }
            }
        }
    }
    __syncthreads();

    // phase D: coalesced transposed write
    int t = tid & 63, c0 = tid >> 6;
    float* ob = out + (size_t)bidx * CC * NNN + n0 + t;
    for (int c = c0; c < CC; c += 4) ob[(size_t)c * NNN] = tile[t * TSTR + c];
}

// ---------------- load-balance loss -------------------------------------------
__global__ void k_lb(float* __restrict__ out, long long out_size) {
    if (threadIdx.x == 0 && out_size > (long long)BB * CC * NNN) {
        float s = 0.f;
#pragma unroll
        for (int e = 0; e < EE; e++) {
            float u = g_usage[e] * (1.0f / TT);
            s += u * u;
        }
        out[(size_t)BB * CC * NNN] = s * (float)EE;
    }
}

// ---------------- launch --------------------------------------------------------
extern "C" void kernel_launch(void* const* d_in, const int* in_sizes, int n_in,
                              void* d_out, int out_size) {
    const float* x     = (const float*)d_in[0];
    const float* wg1   = (const float*)d_in[1];
    const float* bg1   = (const float*)d_in[2];
    const float* gamma = (const float*)d_in[3];
    const float* beta  = (const float*)d_in[4];
    const float* wg2   = (const float*)d_in[5];
    const float* bg2   = (const float*)d_in[6];
    const float* w1    = (const float*)d_in[7];
    const float* b1    = (const float*)d_in[8];
    const float* w2    = (const float*)d_in[9];
    const float* b2    = (const float*)d_in[10];
    float* out = (float*)d_out;

    int smemE = (64 * TSTR + HH * WSTR + 2048) * (int)sizeof(float);   // 174336
    int smemR = (32 * RSTR + 8 * RSTR + 512 + 512 + 256) * (int)sizeof(float); // 87680
    cudaFuncSetAttribute(k_expert, cudaFuncAttributeMaxDynamicSharedMemorySize, smemE);
    cudaFuncSetAttribute(k_gemm,   cudaFuncAttributeMaxDynamicSharedMemorySize, GSMEM);
    cudaFuncSetAttribute(k_route,  cudaFuncAttributeMaxDynamicSharedMemorySize, smemR);

    k_zero<<<1, 512>>>();
    {
        long long tot4 = ((long long)TT * CC + (long long)CC * CC) / 4;
        int nb = (int)((tot4 + 255) / 256);
        k_split<<<nb, 256>>>(x, wg1);
    }
    dim3 gg(CC / 128, TT / 128);
    k_gemm<<<gg, 256, GSMEM>>>(bg1);
    k_route<<<TT / 32, 256, smemR>>>(gamma, beta, wg2, bg2);
    k_fix<<<256, 256>>>(x, wg1, gamma, beta, wg2, bg2);
    k_expert<<<TT / 64, 256, smemE>>>(x, w1, b1, w2, b2, out);
    k_lb<<<1, 32>>>(out, (long long)out_size);
}

// round 6
// speedup vs baseline: 1.6644x; 1.0624x over previous
#include <cuda_runtime.h>
#include <cuda_bf16.h>
#include <math.h>
#include <stdint.h>

#define TT   32768
#define CC   512
#define EE   8
#define HH   16
#define BB   8
#define NNN  4096
#define TSTR 516
#define FIXCAP 8192

// ---------------- scratch (static device globals; no allocation) -------------
__device__ float g_h[(size_t)TT * CC];     // gate hidden, 64MB
__device__ int   g_re[TT * 2];
__device__ float g_rw[TT * 2];
__device__ float g_sum[CC];
__device__ float g_sumsq[CC];
__device__ float g_usage[EE];
__device__ int   g_nfix;
__device__ int   g_fix[FIXCAP];
__device__ __align__(16) __nv_bfloat16 g_xh[(size_t)TT * CC];
__device__ __align__(16) __nv_bfloat16 g_wh[CC * CC];
__device__ __align__(16) __nv_bfloat16 g_wl[CC * CC];

// ---------------- PTX helpers -------------------------------------------------
__device__ __forceinline__ uint32_t smem_u32(const void* p) {
    uint32_t a;
    asm("{ .reg .u64 t; cvta.to.shared.u64 t, %1; cvt.u32.u64 %0, t; }" : "=r"(a) : "l"(p));
    return a;
}
__device__ __forceinline__ void ldm4(uint32_t* r, uint32_t a) {
    asm volatile("ldmatrix.sync.aligned.m8n8.x4.shared.b16 {%0,%1,%2,%3}, [%4];"
                 : "=r"(r[0]), "=r"(r[1]), "=r"(r[2]), "=r"(r[3]) : "r"(a));
}
__device__ __forceinline__ void mma16816(float* d, const uint32_t* a,
                                         uint32_t b0, uint32_t b1) {
    asm volatile(
        "mma.sync.aligned.m16n8k16.row.col.f32.bf16.bf16.f32 "
        "{%0,%1,%2,%3}, {%4,%5,%6,%7}, {%8,%9}, {%0,%1,%2,%3};"
        : "+f"(d[0]), "+f"(d[1]), "+f"(d[2]), "+f"(d[3])
        : "r"(a[0]), "r"(a[1]), "r"(a[2]), "r"(a[3]), "r"(b0), "r"(b1));
}
#define CP16(dst, src) asm volatile("cp.async.cg.shared.global [%0], [%1], 16;" ::"r"(dst), "l"(src) : "memory")
#define CPCOMMIT()     asm volatile("cp.async.commit_group;" ::: "memory")
#define CPWAIT(n)      asm volatile("cp.async.wait_group %0;" ::"n"(n) : "memory")

// ---------------- zero accumulators ------------------------------------------
__global__ void k_zero() {
    int i = threadIdx.x;
    if (i < CC) { g_sum[i] = 0.f; g_sumsq[i] = 0.f; }
    if (i < EE) g_usage[i] = 0.f;
    if (i == 0) g_nfix = 0;
}

// ---------------- bf16 split: xh = bf16(x); wg1 -> wh + wl -------------------
__global__ __launch_bounds__(256) void k_split(const float* __restrict__ x,
                                               const float* __restrict__ wg1) {
    size_t i4 = (size_t)blockIdx.x * 256 + threadIdx.x;
    const size_t nx = (size_t)TT * CC / 4, nw = (size_t)CC * CC / 4;
    if (i4 < nx) {
        float4 v = ((const float4*)x)[i4];
        unsigned hh[4];
        float a[4] = {v.x, v.y, v.z, v.w};
#pragma unroll
        for (int i = 0; i < 4; i++) hh[i] = ((__nv_bfloat16_raw)__float2bfloat16(a[i])).x;
        uint2 ph = {hh[0] | (hh[1] << 16), hh[2] | (hh[3] << 16)};
        ((uint2*)g_xh)[i4] = ph;
    } else if (i4 < nx + nw) {
        size_t o = i4 - nx;
        float4 v = ((const float4*)wg1)[o];
        float a[4] = {v.x, v.y, v.z, v.w};
        unsigned hh[4], ll[4];
#pragma unroll
        for (int i = 0; i < 4; i++) {
            __nv_bfloat16 hb = __float2bfloat16(a[i]);
            __nv_bfloat16 lb = __float2bfloat16(a[i] - __bfloat162float(hb));
            hh[i] = ((__nv_bfloat16_raw)hb).x;
            ll[i] = ((__nv_bfloat16_raw)lb).x;
        }
        uint2 ph = {hh[0] | (hh[1] << 16), hh[2] | (hh[3] << 16)};
        uint2 pl = {ll[0] | (ll[1] << 16), ll[2] | (ll[3] << 16)};
        ((uint2*)g_wh)[o] = ph;
        ((uint2*)g_wl)[o] = pl;
    }
}

// ---------------- gate GEMM1 (HMMA, 2-term, cp.async 2-stage) -----------------
#define STG 49152
#define GSMEM (2 * STG)

__global__ __launch_bounds__(256, 2) void k_gemm(const float* __restrict__ bg1) {
    extern __shared__ char smc[];
    uint32_t sb = smem_u32(smc);
    int tid = threadIdx.x;
    int n0 = blockIdx.x * 128, m0 = blockIdx.y * 128;
    int warp = tid >> 5, lane = tid & 31;
    int wm = warp >> 1, wn = warp & 1;

    const __nv_bfloat16* xs  = g_xh + (size_t)m0 * CC;
    const __nv_bfloat16* whs = g_wh + (size_t)n0 * CC;
    const __nv_bfloat16* wls = g_wl + (size_t)n0 * CC;

    float acc[2][8][4];
#pragma unroll
    for (int i = 0; i < 2; i++)
#pragma unroll
        for (int j = 0; j < 8; j++)
#pragma unroll
            for (int q = 0; q < 4; q++) acc[i][j][q] = 0.f;

    int li = lane & 7, lm = lane >> 3;
    int a_row = (lm & 1) * 8 + li, a_cb = (lm >> 1) * 16;
    int b_row = (lm >> 1) * 8 + li, b_cb = (lm & 1) * 16;

#define LOADSTAGE(S, K0) do {                                                   \
        uint32_t sbs = sb + (S) * STG;                                          \
        const __nv_bfloat16* srcs[3] = {xs, whs, wls};                          \
        _Pragma("unroll")                                                       \
        for (int tt = 0; tt < 3; tt++) {                                        \
            const __nv_bfloat16* src = srcs[tt];                                \
            _Pragma("unroll")                                                   \
            for (int it = 0; it < 4; it++) {                                    \
                int idx = tid + it * 256;                                       \
                int r = idx >> 3, c16 = idx & 7;                                \
                const void* g = src + (size_t)r * CC + (K0) + c16 * 8;          \
                uint32_t bo = (uint32_t)((r << 7) | (c16 << 4));                \
                bo ^= (bo >> 3) & 0x70;                                         \
                CP16(sbs + tt * 16384 + bo, g);                                 \
            }                                                                   \
        }                                                                       \
    } while (0)

    LOADSTAGE(0, 0);
    CPCOMMIT();

    for (int kc = 0; kc < 8; kc++) {
        int s = kc & 1;
        if (kc < 7) {
            LOADSTAGE(s ^ 1, (kc + 1) * 64);
            CPCOMMIT();
            CPWAIT(1);
        } else {
            CPWAIT(0);
        }
        __syncthreads();

        uint32_t abase = sb + s * STG;
#pragma unroll
        for (int tp = 0; tp < 2; tp++) {
            uint32_t bbase = abase + 16384 + tp * 16384;
#pragma unroll
            for (int ks = 0; ks < 4; ks++) {
                int kb = ks * 32;
                uint32_t af[2][4];
#pragma unroll
                for (int mi = 0; mi < 2; mi++) {
                    int r = wm * 32 + mi * 16 + a_row;
                    uint32_t cb = (uint32_t)(kb + a_cb);
                    ldm4(af[mi], abase + (r << 7) + (cb ^ ((r & 7) << 4)));
                }
                uint32_t bfr[4][4];
#pragma unroll
                for (int p = 0; p < 4; p++) {
                    int r = wn * 64 + p * 16 + b_row;
                    uint32_t cb = (uint32_t)(kb + b_cb);
                    ldm4(bfr[p], bbase + (r << 7) + (cb ^ ((r & 7) << 4)));
                }
#pragma unroll
                for (int mi = 0; mi < 2; mi++)
#pragma unroll
                    for (int ni = 0; ni < 8; ni++)
                        mma16816(acc[mi][ni], af[mi],
                                 bfr[ni >> 1][(ni & 1) * 2],
                                 bfr[ni >> 1][(ni & 1) * 2 + 1]);
            }
        }
        __syncthreads();
    }
#undef LOADSTAGE

    int g = lane >> 2, tg = lane & 3;
#pragma unroll
    for (int mi = 0; mi < 2; mi++) {
        int row = m0 + wm * 32 + mi * 16 + g;
#pragma unroll
        for (int ni = 0; ni < 8; ni++) {
            int col = n0 + wn * 64 + ni * 8 + tg * 2;
            float bx = bg1[col], by = bg1[col + 1];
            acc[mi][ni][0] += bx; acc[mi][ni][1] += by;
            acc[mi][ni][2] += bx; acc[mi][ni][3] += by;
            float2 v0 = {acc[mi][ni][0], acc[mi][ni][1]};
            float2 v1 = {acc[mi][ni][2], acc[mi][ni][3]};
            *(float2*)(g_h + (size_t)row * CC + col) = v0;
            *(float2*)(g_h + (size_t)(row + 8) * CC + col) = v1;
        }
    }

    float* ssum = (float*)smc;
    float* ssq  = (float*)(smc + 512);
    if (tid < 128) { ssum[tid] = 0.f; ssq[tid] = 0.f; }
    __syncthreads();
#pragma unroll
    for (int ni = 0; ni < 8; ni++) {
        int colr = wn * 64 + ni * 8 + tg * 2;
        float s0 = 0.f, s1 = 0.f, q0 = 0.f, q1 = 0.f;
#pragma unroll
        for (int mi = 0; mi < 2; mi++) {
            float a0 = acc[mi][ni][0], a1 = acc[mi][ni][1];
            float a2 = acc[mi][ni][2], a3 = acc[mi][ni][3];
            s0 += a0 + a2; s1 += a1 + a3;
            q0 += a0 * a0 + a2 * a2; q1 += a1 * a1 + a3 * a3;
        }
#pragma unroll
        for (int off = 4; off < 32; off <<= 1) {
            s0 += __shfl_xor_sync(0xffffffffu, s0, off);
            s1 += __shfl_xor_sync(0xffffffffu, s1, off);
            q0 += __shfl_xor_sync(0xffffffffu, q0, off);
            q1 += __shfl_xor_sync(0xffffffffu, q1, off);
        }
        if (g == 0) {
            atomicAdd(&ssum[colr], s0); atomicAdd(&ssum[colr + 1], s1);
            atomicAdd(&ssq[colr], q0);  atomicAdd(&ssq[colr + 1], q1);
        }
    }
    __syncthreads();
    if (tid < 128) {
        atomicAdd(&g_sum[n0 + tid], ssum[tid]);
        atomicAdd(&g_sumsq[n0 + tid], ssq[tid]);
    }
}

// ---------------- routing: stream h from gmem, warp-per-token ----------------
// smem: ws[8][516] + scale[512] + shift[512]; ~22KB -> high occupancy.
#define RSTR 516
__global__ __launch_bounds__(256) void k_route(const float* __restrict__ gamma,
                                               const float* __restrict__ beta,
                                               const float* __restrict__ wg2,
                                               const float* __restrict__ bg2) {
    __shared__ float ws[EE * RSTR];
    __shared__ float sc[CC], sh[CC];
    __shared__ float susage[EE];
    __shared__ float sbg2[EE];
    int tid = threadIdx.x, warp = tid >> 5, lane = tid & 31;

    if (tid < EE) { susage[tid] = 0.f; sbg2[tid] = bg2[tid]; }
    for (int c = tid; c < CC; c += 256) {
        float m = g_sum[c] * (1.0f / TT);
        float v = g_sumsq[c] * (1.0f / TT) - m * m;
        float rs = rsqrtf(v + 1e-5f);
        float s = gamma[c] * rs;
        sc[c] = s;
        sh[c] = beta[c] - m * s;
    }
    for (int i4 = tid; i4 < EE * 128; i4 += 256) {
        int e = i4 >> 7, c4 = (i4 & 127) << 2;
        float4 v = *(const float4*)(wg2 + e * CC + c4);
        *(float4*)(ws + e * RSTR + c4) = v;
    }
    __syncthreads();

#pragma unroll
    for (int j = 0; j < 4; j++) {
        int t = blockIdx.x * 32 + warp * 4 + j;
        float p[EE];
#pragma unroll
        for (int e = 0; e < EE; e++) p[e] = 0.f;
#pragma unroll
        for (int i = 0; i < 4; i++) {
            int c4 = i * 128 + lane * 4;
            float4 v = *(const float4*)(g_h + (size_t)t * CC + c4);
            float4 r;
            r.x = fmaxf(sc[c4 + 0] * v.x + sh[c4 + 0], 0.f);
            r.y = fmaxf(sc[c4 + 1] * v.y + sh[c4 + 1], 0.f);
            r.z = fmaxf(sc[c4 + 2] * v.z + sh[c4 + 2], 0.f);
            r.w = fmaxf(sc[c4 + 3] * v.w + sh[c4 + 3], 0.f);
#pragma unroll
            for (int e = 0; e < EE; e++) {
                float4 w = *(const float4*)(ws + e * RSTR + c4);
                p[e] += r.x * w.x + r.y * w.y + r.z * w.z + r.w * w.w;
            }
        }
#pragma unroll
        for (int e = 0; e < EE; e++)
#pragma unroll
            for (int off = 16; off; off >>= 1)
                p[e] += __shfl_xor_sync(0xffffffffu, p[e], off);

        if (lane == 0) {
            float l[EE];
#pragma unroll
            for (int e = 0; e < EE; e++) l[e] = p[e] + sbg2[e];
            int e0 = 0; float v0 = l[0];
#pragma unroll
            for (int e = 1; e < EE; e++) if (l[e] > v0) { v0 = l[e]; e0 = e; }
            int e1 = -1; float v1 = -1e30f;
#pragma unroll
            for (int e = 0; e < EE; e++) if (e != e0 && l[e] > v1) { v1 = l[e]; e1 = e; }
            float v2 = -1e30f;
#pragma unroll
            for (int e = 0; e < EE; e++) if (e != e0 && e != e1 && l[e] > v2) v2 = l[e];
            float ex = expf(v1 - v0);
            float inv = 1.f / (1.f + ex);
            g_re[t * 2] = e0; g_re[t * 2 + 1] = e1;
            g_rw[t * 2] = inv; g_rw[t * 2 + 1] = ex * inv;
            bool flagged = (v1 - v2) < 2.5e-3f;
            if (flagged) {
                int pos = atomicAdd(&g_nfix, 1);
                if (pos < FIXCAP) g_fix[pos] = t; else flagged = false;
            }
            if (!flagged) {
                atomicAdd(&susage[e0], inv);
                atomicAdd(&susage[e1], ex * inv);
            }
        }
    }
    __syncthreads();
    if (tid < EE) atomicAdd(&g_usage[tid], susage[tid]);
}

// ---------------- exact fp32 recompute for near-tie tokens -------------------
__global__ __launch_bounds__(256) void k_fix(const float* __restrict__ x,
                                             const float* __restrict__ wg1,
                                             const float* __restrict__ gamma,
                                             const float* __restrict__ beta,
                                             const float* __restrict__ wg2,
                                             const float* __restrict__ bg2) {
    __shared__ float xr[CC], rr[CC], lg[EE];
    int tid = threadIdx.x, w = tid >> 5, ln = tid & 31;
    int nf = g_nfix; if (nf > FIXCAP) nf = FIXCAP;
    for (int fi = blockIdx.x; fi < nf; fi += gridDim.x) {
        int t = g_fix[fi];
        __syncthreads();
        xr[tid] = x[(size_t)t * CC + tid];
        xr[tid + 256] = x[(size_t)t * CC + tid + 256];
        __syncthreads();
        for (int c = w; c < CC; c += 8) {
            const float* wr = wg1 + (size_t)c * CC;
            float a = 0.f;
#pragma unroll
            for (int j = 0; j < 16; j++) { int k = j * 32 + ln; a += xr[k] * wr[k]; }
#pragma unroll
            for (int off = 16; off; off >>= 1) a += __shfl_xor_sync(0xffffffffu, a, off);
            if (ln == 0) {
                float mu = g_sum[c] * (1.0f / TT);
                float var = g_sumsq[c] * (1.0f / TT) - mu * mu;
                rr[c] = fmaxf(gamma[c] * (a - mu) * rsqrtf(var + 1e-5f) + beta[c], 0.f);
            }
        }
        __syncthreads();
        if (w < EE) {
            const float* we = wg2 + w * CC;
            float a = 0.f;
#pragma unroll
            for (int j = 0; j < 16; j++) { int k = j * 32 + ln; a += rr[k] * we[k]; }
#pragma unroll
            for (int off = 16; off; off >>= 1) a += __shfl_xor_sync(0xffffffffu, a, off);
            if (ln == 0) lg[w] = a + bg2[w];
        }
        __syncthreads();
        if (tid == 0) {
            int e0 = 0; float v0 = lg[0];
#pragma unroll
            for (int e = 1; e < EE; e++) if (lg[e] > v0) { v0 = lg[e]; e0 = e; }
            int e1 = -1; float v1 = -1e30f;
#pragma unroll
            for (int e = 0; e < EE; e++) if (e != e0 && lg[e] > v1) { v1 = lg[e]; e1 = e; }
            float ex = expf(v1 - v0);
            float inv = 1.f / (1.f + ex);
            g_re[t * 2] = e0; g_re[t * 2 + 1] = e1;
            g_rw[t * 2] = inv; g_rw[t * 2 + 1] = ex * inv;
            atomicAdd(&g_usage[e0], inv);
            atomicAdd(&g_usage[e1], ex * inv);
        }
    }
}

// ---------------- experts + weighted combine + transpose ---------------------
// smem: tile 64*516 (x, then out accum) | h1s 64*32. w1 via registers.
__global__ __launch_bounds__(256) void k_expert(const float* __restrict__ x,
                                                const float* __restrict__ w1,
                                                const float* __restrict__ b1,
                                                const float* __restrict__ w2,
                                                const float* __restrict__ b2,
                                                float* __restrict__ out) {
    extern __shared__ float dynsm[];
    float* tile = dynsm;                 // 64*516
    float* h1s  = dynsm + 64 * TSTR;     // 2048

    __shared__ int cnt[EE];
    __shared__ unsigned char lst[EE][64];
    __shared__ float rw[128];

    int tid = threadIdx.x, warp = tid >> 5, lane = tid & 31;
    int tg0 = blockIdx.x * 64;
    int bidx = tg0 >> 12;
    int n0 = tg0 & (NNN - 1);

    // phase A: stage x tile, build routing lists
    for (int idx = tid; idx < 64 * 128; idx += 256) {
        int t = idx >> 7;
        int c = (idx & 127) << 2;
        float4 v = *(const float4*)(x + (size_t)(tg0 + t) * CC + c);
        *(float4*)(tile + t * TSTR + c) = v;
    }
    if (tid < EE) cnt[tid] = 0;
    __syncthreads();
    if (tid < 128) {
        int t = tid >> 1, s = tid & 1;
        int e = g_re[(tg0 + t) * 2 + s];
        rw[tid] = g_rw[(tg0 + t) * 2 + s];
        int p = atomicAdd(&cnt[e], 1);
        lst[e][p] = (unsigned char)tid;
    }
    __syncthreads();

    // phase B: h1 = relu(x @ w1[e] + b1[e])
    // warp = (hgroup = warp&3 -> h in [hg*4, hg*4+4), shalf = warp>>2)
    // lane holds w1^T[h][c] for its 16 channels c = lane*16..+15 (64 regs)
    {
        int hg = warp & 3, shalf = warp >> 2;
        for (int e = 0; e < EE; e++) {
            int m = cnt[e];
            if (m == 0) continue;
            const float* w1e = w1 + (size_t)e * CC * HH + hg * 4;
            float wr[16][4];
#pragma unroll
            for (int cc = 0; cc < 16; cc++) {
                float4 wv = *(const float4*)(w1e + (lane * 16 + cc) * HH);
                wr[cc][0] = wv.x; wr[cc][1] = wv.y; wr[cc][2] = wv.z; wr[cc][3] = wv.w;
            }
            float4 bb = *(const float4*)(b1 + e * HH + hg * 4);
            for (int ii = shalf; ii < m; ii += 2) {
                int ts = lst[e][ii];
                int t = ts >> 1, slot = ts & 1;
                const float* xr = tile + t * TSTR + lane * 16;
                float a0 = 0.f, a1 = 0.f, a2 = 0.f, a3 = 0.f;
#pragma unroll
                for (int cc = 0; cc < 16; cc += 4) {
                    float4 xv = *(const float4*)(xr + cc);
                    a0 += xv.x * wr[cc][0] + xv.y * wr[cc + 1][0] + xv.z * wr[cc + 2][0] + xv.w * wr[cc + 3][0];
                    a1 += xv.x * wr[cc][1] + xv.y * wr[cc + 1][1] + xv.z * wr[cc + 2][1] + xv.w * wr[cc + 3][1];
                    a2 += xv.x * wr[cc][2] + xv.y * wr[cc + 1][2] + xv.z * wr[cc + 2][2] + xv.w * wr[cc + 3][2];
                    a3 += xv.x * wr[cc][3] + xv.y * wr[cc + 1][3] + xv.z * wr[cc + 2][3] + xv.w * wr[cc + 3][3];
                }
#pragma unroll
                for (int off = 16; off; off >>= 1) {
                    a0 += __shfl_xor_sync(0xffffffffu, a0, off);
                    a1 += __shfl_xor_sync(0xffffffffu, a1, off);
                    a2 += __shfl_xor_sync(0xffffffffu, a2, off);
                    a3 += __shfl_xor_sync(0xffffffffu, a3, off);
                }
                if (lane == 0) {
                    float4 o;
                    o.x = fmaxf(a0 + bb.x, 0.f);
                    o.y = fmaxf(a1 + bb.y, 0.f);
                    o.z = fmaxf(a2 + bb.z, 0.f);
                    o.w = fmaxf(a3 + bb.w, 0.f);
                    *(float4*)(h1s + t * 32 + slot * 16 + hg * 4) = o;
                }
            }
        }
    }
    __syncthreads();

    // zero tile (reuse as out accumulator)
    for (int idx = tid; idx < 64 * TSTR; idx += 256) tile[idx] = 0.f;
    __syncthreads();

    // phase C: out[t] += w * (h1 @ w2[e] + b2[e]); thread owns channels tid, tid+256
    {
        int c0 = tid;
        for (int e = 0; e < EE; e++) {
            int m = cnt[e];
            if (m == 0) continue;
            float wA[16], wB[16];
            const float* w2e = w2 + (size_t)e * HH * CC;
#pragma unroll
            for (int k = 0; k < 16; k++) {
                wA[k] = w2e[k * CC + c0];
                wB[k] = w2e[k * CC + c0 + 256];
            }
            float bA = b2[e * CC + c0], bB = b2[e * CC + c0 + 256];
            for (int base = 0; base < m; base += 2) {
                int i1 = base, i2 = (base + 1 < m) ? base + 1 : base;
                int ts1 = lst[e][i1], ts2 = lst[e][i2];
                float wt1 = rw[ts1];
                float wt2 = (base + 1 < m) ? rw[ts2] : 0.f;
                const float* h1 = h1s + (ts1 >> 1) * 32 + (ts1 & 1) * 16;
                const float* h2 = h1s + (ts2 >> 1) * 32 + (ts2 & 1) * 16;
                float aA1 = 0.f, aB1 = 0.f, aA2 = 0.f, aB2 = 0.f;
#pragma unroll
                for (int k4 = 0; k4 < 16; k4 += 4) {
                    float4 hv1 = *(const float4*)(h1 + k4);
                    float4 hv2 = *(const float4*)(h2 + k4);
                    aA1 += hv1.x * wA[k4] + hv1.y * wA[k4 + 1] + hv1.z * wA[k4 + 2] + hv1.w * wA[k4 + 3];
                    aB1 += hv1.x * wB[k4] + hv1.y * wB[k4 + 1] + hv1.z * wB[k4 + 2] + hv1.w * wB[k4 + 3];
                    aA2 += hv2.x * wA[k4] + hv2.y * wA[k4 + 1] + hv2.z * wA[k4 + 2] + hv2.w * wA[k4 + 3];
                    aB2 += hv2.x * wB[k4] + hv2.y * wB[k4 + 1] + hv2.z * wB[k4 + 2] + hv2.w * wB[k4 + 3];
                }
                float* tr1 = tile + (ts1 >> 1) * TSTR;
                float* tr2 = tile + (ts2 >> 1) * TSTR;
                tr1[c0]       += wt1 * (aA1 + bA);
                tr1[c0 + 256] += wt1 * (aB1 + bB);
                tr2[c0]       += wt2 * (aA2 + bA);
                tr2[c0 + 256] += wt2 * (aB2 + bB);
            }
        }
    }
    __syncthreads();

    // phase D: coalesced transposed write
    int t = tid & 63, c0 = tid >> 6;
    float* ob = out + (size_t)bidx * CC * NNN + n0 + t;
    for (int c = c0; c < CC; c += 4) ob[(size_t)c * NNN] = tile[t * TSTR + c];
}

// ---------------- load-balance loss -------------------------------------------
__global__ void k_lb(float* __restrict__ out, long long out_size) {
    if (threadIdx.x == 0 && out_size > (long long)BB * CC * NNN) {
        float s = 0.f;
#pragma unroll
        for (int e = 0; e < EE; e++) {
            float u = g_usage[e] * (1.0f / TT);
            s += u * u;
        }
        out[(size_t)BB * CC * NNN] = s * (float)EE;
    }
}

// ---------------- launch --------------------------------------------------------
extern "C" void kernel_launch(void* const* d_in, const int* in_sizes, int n_in,
                              void* d_out, int out_size) {
    const float* x     = (const float*)d_in[0];
    const float* wg1   = (const float*)d_in[1];
    const float* bg1   = (const float*)d_in[2];
    const float* gamma = (const float*)d_in[3];
    const float* beta  = (const float*)d_in[4];
    const float* wg2   = (const float*)d_in[5];
    const float* bg2   = (const float*)d_in[6];
    const float* w1    = (const float*)d_in[7];
    const float* b1    = (const float*)d_in[8];
    const float* w2    = (const float*)d_in[9];
    const float* b2    = (const float*)d_in[10];
    float* out = (float*)d_out;

    int smemE = (64 * TSTR + 2048) * (int)sizeof(float);   // 140288
    cudaFuncSetAttribute(k_expert, cudaFuncAttributeMaxDynamicSharedMemorySize, smemE);
    cudaFuncSetAttribute(k_gemm,   cudaFuncAttributeMaxDynamicSharedMemorySize, GSMEM);

    k_zero<<<1, 512>>>();
    {
        long long tot4 = ((long long)TT * CC + (long long)CC * CC) / 4;
        int nb = (int)((tot4 + 255) / 256);
        k_split<<<nb, 256>>>(x, wg1);
    }
    dim3 gg(CC / 128, TT / 128);
    k_gemm<<<gg, 256, GSMEM>>>(bg1);
    k_route<<<TT / 32, 256>>>(gamma, beta, wg2, bg2);
    k_fix<<<256, 256>>>(x, wg1, gamma, beta, wg2, bg2);
    k_expert<<<TT / 64, 256, smemE>>>(x, w1, b1, w2, b2, out);
    k_lb<<<1, 32>>>(out, (long long)out_size);
}

// round 9
// speedup vs baseline: 2.1939x; 1.3182x over previous
#include <cuda_runtime.h>
#include <cuda_bf16.h>
#include <math.h>
#include <stdint.h>

#define TT   32768
#define CC   512
#define EE   8
#define HH   16
#define BB   8
#define NNN  4096
#define FIXCAP 8192

// ---------------- scratch (static device globals; no allocation) -------------
__device__ float g_h[(size_t)TT * CC];     // gate hidden, 64MB
__device__ float g_h1[(size_t)TT * 128];   // expert hidden (all experts), 16MB
__device__ int   g_re[TT * 2];
__device__ float g_rw[TT * 2];
__device__ float g_sum[CC];
__device__ float g_sumsq[CC];
__device__ float g_usage[EE];
__device__ int   g_nfix;
__device__ int   g_fix[FIXCAP];
__device__ __align__(16) __nv_bfloat16 g_xh[(size_t)TT * CC];
__device__ __align__(16) __nv_bfloat16 g_xl[(size_t)TT * CC];
__device__ __align__(16) __nv_bfloat16 g_wh[CC * CC];
__device__ __align__(16) __nv_bfloat16 g_wl[CC * CC];
__device__ __align__(16) __nv_bfloat16 g_w1h[128 * CC];   // W1cat^T [n=e*16+h][k=c]
__device__ __align__(16) __nv_bfloat16 g_w1l[128 * CC];
__device__ __align__(16) __nv_bfloat16 g_w2h[CC * 128];   // W2cat^T [n=c][k=e*16+h]
__device__ __align__(16) __nv_bfloat16 g_w2l[CC * 128];
__device__ __align__(16) __nv_bfloat16 g_ah[(size_t)TT * 128];  // h1scaled hi
__device__ __align__(16) __nv_bfloat16 g_al[(size_t)TT * 128];  // h1scaled lo

// ---------------- PTX helpers -------------------------------------------------
__device__ __forceinline__ uint32_t smem_u32(const void* p) {
    uint32_t a;
    asm("{ .reg .u64 t; cvta.to.shared.u64 t, %1; cvt.u32.u64 %0, t; }" : "=r"(a) : "l"(p));
    return a;
}
__device__ __forceinline__ void ldm4(uint32_t* r, uint32_t a) {
    asm volatile("ldmatrix.sync.aligned.m8n8.x4.shared.b16 {%0,%1,%2,%3}, [%4];"
                 : "=r"(r[0]), "=r"(r[1]), "=r"(r[2]), "=r"(r[3]) : "r"(a));
}
__device__ __forceinline__ void mma16816(float* d, const uint32_t* a,
                                         uint32_t b0, uint32_t b1) {
    asm volatile(
        "mma.sync.aligned.m16n8k16.row.col.f32.bf16.bf16.f32 "
        "{%0,%1,%2,%3}, {%4,%5,%6,%7}, {%8,%9}, {%0,%1,%2,%3};"
        : "+f"(d[0]), "+f"(d[1]), "+f"(d[2]), "+f"(d[3])
        : "r"(a[0]), "r"(a[1]), "r"(a[2]), "r"(a[3]), "r"(b0), "r"(b1));
}
#define CP16(dst, src) asm volatile("cp.async.cg.shared.global [%0], [%1], 16;" ::"r"(dst), "l"(src) : "memory")
#define CPCOMMIT()     asm volatile("cp.async.commit_group;" ::: "memory")
#define CPWAIT(n)      asm volatile("cp.async.wait_group %0;" ::"n"(n) : "memory")

// ---------------- zero accumulators ------------------------------------------
__global__ void k_zero() {
    int i = threadIdx.x;
    if (i < CC) { g_sum[i] = 0.f; g_sumsq[i] = 0.f; }
    if (i < EE) g_usage[i] = 0.f;
    if (i == 0) g_nfix = 0;
}

// ---------------- bf16 splits --------------------------------------------------
__global__ __launch_bounds__(256) void k_split(const float* __restrict__ x,
                                               const float* __restrict__ wg1) {
    size_t i4 = (size_t)blockIdx.x * 256 + threadIdx.x;
    const size_t nx = (size_t)TT * CC / 4, nw = (size_t)CC * CC / 4;
    const float* s; __nv_bfloat16 *dh, *dl; size_t o;
    if (i4 < nx)           { s = x;   o = i4;      dh = g_xh; dl = g_xl; }
    else if (i4 < nx + nw) { s = wg1; o = i4 - nx; dh = g_wh; dl = g_wl; }
    else return;
    float4 v = ((const float4*)s)[o];
    float a[4] = {v.x, v.y, v.z, v.w};
    unsigned hh[4], ll[4];
#pragma unroll
    for (int i = 0; i < 4; i++) {
        __nv_bfloat16 hb = __float2bfloat16(a[i]);
        __nv_bfloat16 lb = __float2bfloat16(a[i] - __bfloat162float(hb));
        hh[i] = ((__nv_bfloat16_raw)hb).x;
        ll[i] = ((__nv_bfloat16_raw)lb).x;
    }
    uint2 ph = {hh[0] | (hh[1] << 16), hh[2] | (hh[3] << 16)};
    uint2 pl = {ll[0] | (ll[1] << 16), ll[2] | (ll[3] << 16)};
    ((uint2*)dh)[o] = ph;
    ((uint2*)dl)[o] = pl;
}

// expert weight repack + split: w1 [E,C,H] -> g_w1h/l [e*16+h][c]; w2 [E,H,C] -> g_w2h/l [c][e*16+h]
__global__ __launch_bounds__(256) void k_split2(const float* __restrict__ w1,
                                                const float* __restrict__ w2) {
    int idx = blockIdx.x * 256 + threadIdx.x;
    if (idx < 65536) {
        int e = idx >> 13, r = idx & 8191, c = r >> 4, h = r & 15;
        float v = w1[idx];
        __nv_bfloat16 hb = __float2bfloat16(v);
        __nv_bfloat16 lb = __float2bfloat16(v - __bfloat162float(hb));
        int n = e * 16 + h;
        g_w1h[n * CC + c] = hb;
        g_w1l[n * CC + c] = lb;
    } else if (idx < 131072) {
        int j = idx - 65536;
        int e = j >> 13, r = j & 8191, h = r >> 9, c = r & 511;
        float v = w2[j];
        __nv_bfloat16 hb = __float2bfloat16(v);
        __nv_bfloat16 lb = __float2bfloat16(v - __bfloat162float(hb));
        int n = e * 16 + h;
        g_w2h[c * 128 + n] = hb;
        g_w2l[c * 128 + n] = lb;
    }
}

// ---------------- gate GEMM1 (HMMA, 2-term, cp.async 2-stage) -----------------
#define STG 49152
#define GSMEM (2 * STG)

__global__ __launch_bounds__(256, 2) void k_gemm(const float* __restrict__ bg1) {
    extern __shared__ char smc[];
    uint32_t sb = smem_u32(smc);
    int tid = threadIdx.x;
    int n0 = blockIdx.x * 128, m0 = blockIdx.y * 128;
    int warp = tid >> 5, lane = tid & 31;
    int wm = warp >> 1, wn = warp & 1;

    const __nv_bfloat16* xs  = g_xh + (size_t)m0 * CC;
    const __nv_bfloat16* whs = g_wh + (size_t)n0 * CC;
    const __nv_bfloat16* wls = g_wl + (size_t)n0 * CC;

    float acc[2][8][4];
#pragma unroll
    for (int i = 0; i < 2; i++)
#pragma unroll
        for (int j = 0; j < 8; j++)
#pragma unroll
            for (int q = 0; q < 4; q++) acc[i][j][q] = 0.f;

    int li = lane & 7, lm = lane >> 3;
    int a_row = (lm & 1) * 8 + li, a_cb = (lm >> 1) * 16;
    int b_row = (lm >> 1) * 8 + li, b_cb = (lm & 1) * 16;

#define LOADSTAGE(S, K0) do {                                                   \
        uint32_t sbs = sb + (S) * STG;                                          \
        const __nv_bfloat16* srcs[3] = {xs, whs, wls};                          \
        _Pragma("unroll")                                                       \
        for (int tt = 0; tt < 3; tt++) {                                        \
            const __nv_bfloat16* src = srcs[tt];                                \
            _Pragma("unroll")                                                   \
            for (int it = 0; it < 4; it++) {                                    \
                int idx = tid + it * 256;                                       \
                int r = idx >> 3, c16 = idx & 7;                                \
                const void* g = src + (size_t)r * CC + (K0) + c16 * 8;          \
                uint32_t bo = (uint32_t)((r << 7) | (c16 << 4));                \
                bo ^= (bo >> 3) & 0x70;                                         \
                CP16(sbs + tt * 16384 + bo, g);                                 \
            }                                                                   \
        }                                                                       \
    } while (0)

    LOADSTAGE(0, 0);
    CPCOMMIT();

    for (int kc = 0; kc < 8; kc++) {
        int s = kc & 1;
        if (kc < 7) {
            LOADSTAGE(s ^ 1, (kc + 1) * 64);
            CPCOMMIT();
            CPWAIT(1);
        } else {
            CPWAIT(0);
        }
        __syncthreads();

        uint32_t abase = sb + s * STG;
#pragma unroll
        for (int tp = 0; tp < 2; tp++) {
            uint32_t bbase = abase + 16384 + tp * 16384;
#pragma unroll
            for (int ks = 0; ks < 4; ks++) {
                int kb = ks * 32;
                uint32_t af[2][4];
#pragma unroll
                for (int mi = 0; mi < 2; mi++) {
                    int r = wm * 32 + mi * 16 + a_row;
                    uint32_t cb = (uint32_t)(kb + a_cb);
                    ldm4(af[mi], abase + (r << 7) + (cb ^ ((r & 7) << 4)));
                }
                uint32_t bfr[4][4];
#pragma unroll
                for (int p = 0; p < 4; p++) {
                    int r = wn * 64 + p * 16 + b_row;
                    uint32_t cb = (uint32_t)(kb + b_cb);
                    ldm4(bfr[p], bbase + (r << 7) + (cb ^ ((r & 7) << 4)));
                }
#pragma unroll
                for (int mi = 0; mi < 2; mi++)
#pragma unroll
                    for (int ni = 0; ni < 8; ni++)
                        mma16816(acc[mi][ni], af[mi],
                                 bfr[ni >> 1][(ni & 1) * 2],
                                 bfr[ni >> 1][(ni & 1) * 2 + 1]);
            }
        }
        __syncthreads();
    }
#undef LOADSTAGE

    int g = lane >> 2, tg = lane & 3;
#pragma unroll
    for (int mi = 0; mi < 2; mi++) {
        int row = m0 + wm * 32 + mi * 16 + g;
#pragma unroll
        for (int ni = 0; ni < 8; ni++) {
            int col = n0 + wn * 64 + ni * 8 + tg * 2;
            float bx = bg1[col], by = bg1[col + 1];
            acc[mi][ni][0] += bx; acc[mi][ni][1] += by;
            acc[mi][ni][2] += bx; acc[mi][ni][3] += by;
            float2 v0 = {acc[mi][ni][0], acc[mi][ni][1]};
            float2 v1 = {acc[mi][ni][2], acc[mi][ni][3]};
            *(float2*)(g_h + (size_t)row * CC + col) = v0;
            *(float2*)(g_h + (size_t)(row + 8) * CC + col) = v1;
        }
    }

    float* ssum = (float*)smc;
    float* ssq  = (float*)(smc + 512);
    if (tid < 128) { ssum[tid] = 0.f; ssq[tid] = 0.f; }
    __syncthreads();
#pragma unroll
    for (int ni = 0; ni < 8; ni++) {
        int colr = wn * 64 + ni * 8 + tg * 2;
        float s0 = 0.f, s1 = 0.f, q0 = 0.f, q1 = 0.f;
#pragma unroll
        for (int mi = 0; mi < 2; mi++) {
            float a0 = acc[mi][ni][0], a1 = acc[mi][ni][1];
            float a2 = acc[mi][ni][2], a3 = acc[mi][ni][3];
            s0 += a0 + a2; s1 += a1 + a3;
            q0 += a0 * a0 + a2 * a2; q1 += a1 * a1 + a3 * a3;
        }
#pragma unroll
        for (int off = 4; off < 32; off <<= 1) {
            s0 += __shfl_xor_sync(0xffffffffu, s0, off);
            s1 += __shfl_xor_sync(0xffffffffu, s1, off);
            q0 += __shfl_xor_sync(0xffffffffu, q0, off);
            q1 += __shfl_xor_sync(0xffffffffu, q1, off);
        }
        if (g == 0) {
            atomicAdd(&ssum[colr], s0); atomicAdd(&ssum[colr + 1], s1);
            atomicAdd(&ssq[colr], q0);  atomicAdd(&ssq[colr + 1], q1);
        }
    }
    __syncthreads();
    if (tid < 128) {
        atomicAdd(&g_sum[n0 + tid], ssum[tid]);
        atomicAdd(&g_sumsq[n0 + tid], ssq[tid]);
    }
}

// ---------------- expert GEMM1: h1all = relu(x @ W1cat + b1) (3-term) --------
// M=T, N=128, K=512. Tile 128x128, BK=64. Stage = Ah|Al|Bh|Bl = 64KB, 2 stages.
#define ESMEM 131072

__global__ __launch_bounds__(256, 1) void k_egemm1(const float* __restrict__ b1) {
    extern __shared__ char smc[];
    uint32_t sb = smem_u32(smc);
    int tid = threadIdx.x;
    int m0 = blockIdx.x * 128;
    int warp = tid >> 5, lane = tid & 31;
    int wm = warp >> 1, wn = warp & 1;

    const __nv_bfloat16* ah = g_xh + (size_t)m0 * CC;
    const __nv_bfloat16* al = g_xl + (size_t)m0 * CC;

    float acc[2][8][4];
#pragma unroll
    for (int i = 0; i < 2; i++)
#pragma unroll
        for (int j = 0; j < 8; j++)
#pragma unroll
            for (int q = 0; q < 4; q++) acc[i][j][q] = 0.f;

    int li = lane & 7, lm = lane >> 3;
    int a_row = (lm & 1) * 8 + li, a_cb = (lm >> 1) * 16;
    int b_row = (lm >> 1) * 8 + li, b_cb = (lm & 1) * 16;

#define LOADS1(S, K0) do {                                                      \
        uint32_t sbs = sb + (S) * 65536;                                        \
        const __nv_bfloat16* srcs[4] = {ah, al, g_w1h, g_w1l};                  \
        _Pragma("unroll")                                                       \
        for (int tt = 0; tt < 4; tt++) {                                        \
            const __nv_bfloat16* src = srcs[tt];                                \
            _Pragma("unroll")                                                   \
            for (int it = 0; it < 4; it++) {                                    \
                int idx = tid + it * 256;                                       \
                int r = idx >> 3, c16 = idx & 7;                                \
                const void* g = src + (size_t)r * CC + (K0) + c16 * 8;          \
                uint32_t bo = (uint32_t)((r << 7) | (c16 << 4));                \
                bo ^= (bo >> 3) & 0x70;                                         \
                CP16(sbs + tt * 16384 + bo, g);                                 \
            }                                                                   \
        }                                                                       \
    } while (0)

    LOADS1(0, 0);
    CPCOMMIT();

    const int aoff[3] = {0, 0, 16384};
    const int boff[3] = {32768, 49152, 32768};

    for (int kc = 0; kc < 8; kc++) {
        int s = kc & 1;
        if (kc < 7) {
            LOADS1(s ^ 1, (kc + 1) * 64);
            CPCOMMIT();
            CPWAIT(1);
        } else {
            CPWAIT(0);
        }
        __syncthreads();

#pragma unroll
        for (int tp = 0; tp < 3; tp++) {
            uint32_t abase = sb + s * 65536 + aoff[tp];
            uint32_t bbase = sb + s * 65536 + boff[tp];
#pragma unroll
            for (int ks = 0; ks < 4; ks++) {
                int kb = ks * 32;
                uint32_t af[2][4];
#pragma unroll
                for (int mi = 0; mi < 2; mi++) {
                    int r = wm * 32 + mi * 16 + a_row;
                    uint32_t cb = (uint32_t)(kb + a_cb);
                    ldm4(af[mi], abase + (r << 7) + (cb ^ ((r & 7) << 4)));
                }
                uint32_t bfr[4][4];
#pragma unroll
                for (int p = 0; p < 4; p++) {
                    int r = wn * 64 + p * 16 + b_row;
                    uint32_t cb = (uint32_t)(kb + b_cb);
                    ldm4(bfr[p], bbase + (r << 7) + (cb ^ ((r & 7) << 4)));
                }
#pragma unroll
                for (int mi = 0; mi < 2; mi++)
#pragma unroll
                    for (int ni = 0; ni < 8; ni++)
                        mma16816(acc[mi][ni], af[mi],
                                 bfr[ni >> 1][(ni & 1) * 2],
                                 bfr[ni >> 1][(ni & 1) * 2 + 1]);
            }
        }
        __syncthreads();
    }
#undef LOADS1

    int g = lane >> 2, tg = lane & 3;
#pragma unroll
    for (int mi = 0; mi < 2; mi++) {
        int row = m0 + wm * 32 + mi * 16 + g;
#pragma unroll
        for (int ni = 0; ni < 8; ni++) {
            int col = wn * 64 + ni * 8 + tg * 2;
            float bx = b1[col], by = b1[col + 1];
            float2 v0 = {fmaxf(acc[mi][ni][0] + bx, 0.f), fmaxf(acc[mi][ni][1] + by, 0.f)};
            float2 v1 = {fmaxf(acc[mi][ni][2] + bx, 0.f), fmaxf(acc[mi][ni][3] + by, 0.f)};
            *(float2*)(g_h1 + (size_t)row * 128 + col) = v0;
            *(float2*)(g_h1 + (size_t)(row + 8) * 128 + col) = v1;
        }
    }
}

// ---------------- routing: stream h from gmem, warp-per-token ----------------
#define RSTR 516
__global__ __launch_bounds__(256) void k_route(const float* __restrict__ gamma,
                                               const float* __restrict__ beta,
                                               const float* __restrict__ wg2,
                                               const float* __restrict__ bg2) {
    __shared__ float ws[EE * RSTR];
    __shared__ float sc[CC], sh[CC];
    __shared__ float susage[EE];
    __shared__ float sbg2[EE];
    int tid = threadIdx.x, warp = tid >> 5, lane = tid & 31;

    if (tid < EE) { susage[tid] = 0.f; sbg2[tid] = bg2[tid]; }
    for (int c = tid; c < CC; c += 256) {
        float m = g_sum[c] * (1.0f / TT);
        float v = g_sumsq[c] * (1.0f / TT) - m * m;
        float rs = rsqrtf(v + 1e-5f);
        float s = gamma[c] * rs;
        sc[c] = s;
        sh[c] = beta[c] - m * s;
    }
    for (int i4 = tid; i4 < EE * 128; i4 += 256) {
        int e = i4 >> 7, c4 = (i4 & 127) << 2;
        float4 v = *(const float4*)(wg2 + e * CC + c4);
        *(float4*)(ws + e * RSTR + c4) = v;
    }
    __syncthreads();

#pragma unroll 1
    for (int j = 0; j < 4; j++) {
        int t = blockIdx.x * 32 + warp * 4 + j;
        float p[EE];
#pragma unroll
        for (int e = 0; e < EE; e++) p[e] = 0.f;
#pragma unroll 1
        for (int i = 0; i < 4; i++) {
            int c4 = i * 128 + lane * 4;
            float4 v = *(const float4*)(g_h + (size_t)t * CC + c4);
            float4 r;
            r.x = fmaxf(sc[c4 + 0] * v.x + sh[c4 + 0], 0.f);
            r.y = fmaxf(sc[c4 + 1] * v.y + sh[c4 + 1], 0.f);
            r.z = fmaxf(sc[c4 + 2] * v.z + sh[c4 + 2], 0.f);
            r.w = fmaxf(sc[c4 + 3] * v.w + sh[c4 + 3], 0.f);
#pragma unroll
            for (int e = 0; e < EE; e++) {
                float4 w = *(const float4*)(ws + e * RSTR + c4);
                p[e] += r.x * w.x + r.y * w.y + r.z * w.z + r.w * w.w;
            }
        }
#pragma unroll
        for (int e = 0; e < EE; e++)
#pragma unroll
            for (int off = 16; off; off >>= 1)
                p[e] += __shfl_xor_sync(0xffffffffu, p[e], off);

        if (lane == 0) {
            float l[EE];
#pragma unroll
            for (int e = 0; e < EE; e++) l[e] = p[e] + sbg2[e];
            int e0 = 0; float v0 = l[0];
#pragma unroll
            for (int e = 1; e < EE; e++) if (l[e] > v0) { v0 = l[e]; e0 = e; }
            int e1 = -1; float v1 = -1e30f;
#pragma unroll
            for (int e = 0; e < EE; e++) if (e != e0 && l[e] > v1) { v1 = l[e]; e1 = e; }
            float v2 = -1e30f;
#pragma unroll
            for (int e = 0; e < EE; e++) if (e != e0 && e != e1 && l[e] > v2) v2 = l[e];
            float ex = expf(v1 - v0);
            float inv = 1.f / (1.f + ex);
            g_re[t * 2] = e0; g_re[t * 2 + 1] = e1;
            g_rw[t * 2] = inv; g_rw[t * 2 + 1] = ex * inv;
            bool flagged = (v1 - v2) < 2.5e-3f;
            if (flagged) {
                int pos = atomicAdd(&g_nfix, 1);
                if (pos < FIXCAP) g_fix[pos] = t; else flagged = false;
            }
            if (!flagged) {
                atomicAdd(&susage[e0], inv);
                atomicAdd(&susage[e1], ex * inv);
            }
        }
    }
    __syncthreads();
    if (tid < EE) atomicAdd(&g_usage[tid], susage[tid]);
}

// ---------------- exact fp32 recompute for near-tie tokens -------------------
__global__ __launch_bounds__(256) void k_fix(const float* __restrict__ x,
                                             const float* __restrict__ wg1,
                                             const float* __restrict__ gamma,
                                             const float* __restrict__ beta,
                                             const float* __restrict__ wg2,
                                             const float* __restrict__ bg2) {
    __shared__ float xr[CC], rr[CC], lg[EE];
    int tid = threadIdx.x, w = tid >> 5, ln = tid & 31;
    int nf = g_nfix; if (nf > FIXCAP) nf = FIXCAP;
    for (int fi = blockIdx.x; fi < nf; fi += gridDim.x) {
        int t = g_fix[fi];
        __syncthreads();
        xr[tid] = x[(size_t)t * CC + tid];
        xr[tid + 256] = x[(size_t)t * CC + tid + 256];
        __syncthreads();
        for (int c = w; c < CC; c += 8) {
            const float* wr = wg1 + (size_t)c * CC;
            float a = 0.f;
#pragma unroll
            for (int j = 0; j < 16; j++) { int k = j * 32 + ln; a += xr[k] * wr[k]; }
#pragma unroll
            for (int off = 16; off; off >>= 1) a += __shfl_xor_sync(0xffffffffu, a, off);
            if (ln == 0) {
                float mu = g_sum[c] * (1.0f / TT);
                float var = g_sumsq[c] * (1.0f / TT) - mu * mu;
                rr[c] = fmaxf(gamma[c] * (a - mu) * rsqrtf(var + 1e-5f) + beta[c], 0.f);
            }
        }
        __syncthreads();
        if (w < EE) {
            const float* we = wg2 + w * CC;
            float a = 0.f;
#pragma unroll
            for (int j = 0; j < 16; j++) { int k = j * 32 + ln; a += rr[k] * we[k]; }
#pragma unroll
            for (int off = 16; off; off >>= 1) a += __shfl_xor_sync(0xffffffffu, a, off);
            if (ln == 0) lg[w] = a + bg2[w];
        }
        __syncthreads();
        if (tid == 0) {
            int e0 = 0; float v0 = lg[0];
#pragma unroll
            for (int e = 1; e < EE; e++) if (lg[e] > v0) { v0 = lg[e]; e0 = e; }
            int e1 = -1; float v1 = -1e30f;
#pragma unroll
            for (int e = 0; e < EE; e++) if (e != e0 && lg[e] > v1) { v1 = lg[e]; e1 = e; }
            float ex = expf(v1 - v0);
            float inv = 1.f / (1.f + ex);
            g_re[t * 2] = e0; g_re[t * 2 + 1] = e1;
            g_rw[t * 2] = inv; g_rw[t * 2 + 1] = ex * inv;
            atomicAdd(&g_usage[e0], inv);
            atomicAdd(&g_usage[e1], ex * inv);
        }
    }
}

// ---------------- scale h1 by routing weights, split to bf16 hi/lo ------------
__global__ __launch_bounds__(256) void k_scale() {
    int idx4 = blockIdx.x * 256 + threadIdx.x;       // over T*128/4
    int t = idx4 >> 5;
    int k4 = (idx4 & 31) << 2;
    int e = k4 >> 4;
    int e0 = __ldg(&g_re[t * 2]), e1 = __ldg(&g_re[t * 2 + 1]);
    float w = (e == e0) ? __ldg(&g_rw[t * 2]) : ((e == e1) ? __ldg(&g_rw[t * 2 + 1]) : 0.f);
    float4 v = *(const float4*)(g_h1 + (size_t)t * 128 + k4);
    float a[4] = {w * v.x, w * v.y, w * v.z, w * v.w};
    unsigned hh[4], ll[4];
#pragma unroll
    for (int i = 0; i < 4; i++) {
        __nv_bfloat16 hb = __float2bfloat16(a[i]);
        __nv_bfloat16 lb = __float2bfloat16(a[i] - __bfloat162float(hb));
        hh[i] = ((__nv_bfloat16_raw)hb).x;
        ll[i] = ((__nv_bfloat16_raw)lb).x;
    }
    uint2 ph = {hh[0] | (hh[1] << 16), hh[2] | (hh[3] << 16)};
    uint2 pl = {ll[0] | (ll[1] << 16), ll[2] | (ll[3] << 16)};
    ((uint2*)g_ah)[idx4] = ph;
    ((uint2*)g_al)[idx4] = pl;
}

// ---------------- expert GEMM2 + weighted bias + transpose -------------------
// out[b][c][n] = (h1scaled @ W2cat)[t][c] + sum_s rw[t,s]*b2[e_s,c]
// M=T, N=512, K=128. Tile 128x128, BK=64, 2 chunks. 3-term.
__global__ __launch_bounds__(256, 1) void k_egemm2(const float* __restrict__ b2,
                                                   float* __restrict__ out) {
    extern __shared__ char smc[];
    uint32_t sb = smem_u32(smc);
    int tid = threadIdx.x;
    int n0 = blockIdx.x * 128, m0 = blockIdx.y * 128;
    int warp = tid >> 5, lane = tid & 31;
    int wm = warp >> 1, wn = warp & 1;

    const __nv_bfloat16* ah = g_ah + (size_t)m0 * 128;
    const __nv_bfloat16* al = g_al + (size_t)m0 * 128;
    const __nv_bfloat16* bh = g_w2h + (size_t)n0 * 128;
    const __nv_bfloat16* bl = g_w2l + (size_t)n0 * 128;

    float acc[2][8][4];
#pragma unroll
    for (int i = 0; i < 2; i++)
#pragma unroll
        for (int j = 0; j < 8; j++)
#pragma unroll
            for (int q = 0; q < 4; q++) acc[i][j][q] = 0.f;

    int li = lane & 7, lm = lane >> 3;
    int a_row = (lm & 1) * 8 + li, a_cb = (lm >> 1) * 16;
    int b_row = (lm >> 1) * 8 + li, b_cb = (lm & 1) * 16;

#define LOADS2(S, K0) do {                                                      \
        uint32_t sbs = sb + (S) * 65536;                                        \
        const __nv_bfloat16* srcs[4] = {ah, al, bh, bl};                        \
        _Pragma("unroll")                                                       \
        for (int tt = 0; tt < 4; tt++) {                                        \
            const __nv_bfloat16* src = srcs[tt];                                \
            _Pragma("unroll")                                                   \
            for (int it = 0; it < 4; it++) {                                    \
                int idx = tid + it * 256;                                       \
                int r = idx >> 3, c16 = idx & 7;                                \
                const void* g = src + (size_t)r * 128 + (K0) + c16 * 8;         \
                uint32_t bo = (uint32_t)((r << 7) | (c16 << 4));                \
                bo ^= (bo >> 3) & 0x70;                                         \
                CP16(sbs + tt * 16384 + bo, g);                                 \
            }                                                                   \
        }                                                                       \
    } while (0)

    LOADS2(0, 0);
    CPCOMMIT();

    const int aoff[3] = {0, 0, 16384};
    const int boff[3] = {32768, 49152, 32768};

    for (int kc = 0; kc < 2; kc++) {
        int s = kc & 1;
        if (kc < 1) {
            LOADS2(1, 64);
            CPCOMMIT();
            CPWAIT(1);
        } else {
            CPWAIT(0);
        }
        __syncthreads();

#pragma unroll
        for (int tp = 0; tp < 3; tp++) {
            uint32_t abase = sb + s * 65536 + aoff[tp];
            uint32_t bbase = sb + s * 65536 + boff[tp];
#pragma unroll
            for (int ks = 0; ks < 4; ks++) {
                int kb = ks * 32;
                uint32_t af[2][4];
#pragma unroll
                for (int mi = 0; mi < 2; mi++) {
                    int r = wm * 32 + mi * 16 + a_row;
                    uint32_t cb = (uint32_t)(kb + a_cb);
                    ldm4(af[mi], abase + (r << 7) + (cb ^ ((r & 7) << 4)));
                }
                uint32_t bfr[4][4];
#pragma unroll
                for (int p = 0; p < 4; p++) {
                    int r = wn * 64 + p * 16 + b_row;
                    uint32_t cb = (uint32_t)(kb + b_cb);
                    ldm4(bfr[p], bbase + (r << 7) + (cb ^ ((r & 7) << 4)));
                }
#pragma unroll
                for (int mi = 0; mi < 2; mi++)
#pragma unroll
                    for (int ni = 0; ni < 8; ni++)
                        mma16816(acc[mi][ni], af[mi],
                                 bfr[ni >> 1][(ni & 1) * 2],
                                 bfr[ni >> 1][(ni & 1) * 2 + 1]);
            }
        }
        __syncthreads();
    }
#undef LOADS2

    // epilogue: stage to smem, add weighted bias, transposed store
    float* ot  = (float*)smc;            // 128 x 129
    float* b2s = ot + 128 * 129;         // 8 x 128 (this block's channel slice)
    float* srw = b2s + 1024;             // 256
    int*   sre = (int*)(srw + 256);      // 256

    int g = lane >> 2, tg = lane & 3;
#pragma unroll
    for (int mi = 0; mi < 2; mi++) {
        int rl = wm * 32 + mi * 16 + g;
#pragma unroll
        for (int ni = 0; ni < 8; ni++) {
            int cl = wn * 64 + ni * 8 + tg * 2;
            ot[rl * 129 + cl] = acc[mi][ni][0];
            ot[rl * 129 + cl + 1] = acc[mi][ni][1];
            ot[(rl + 8) * 129 + cl] = acc[mi][ni][2];
            ot[(rl + 8) * 129 + cl + 1] = acc[mi][ni][3];
        }
    }
    if (tid < 256) {
        sre[tid] = g_re[m0 * 2 + tid];
        srw[tid] = g_rw[m0 * 2 + tid];
    }
    for (int i = tid; i < 1024; i += 256) {
        int e = i >> 7, cl = i & 127;
        b2s[i] = b2[e * CC + n0 + cl];
    }
    __syncthreads();

    int c = tid >> 1, half = tid & 1;
    int batch = m0 >> 12, nb = m0 & (NNN - 1);
    float* ob = out + (size_t)batch * CC * NNN + (size_t)(n0 + c) * NNN + nb + half * 64;
#pragma unroll 2
    for (int tt4 = 0; tt4 < 64; tt4 += 4) {
        float4 v;
        float vv[4];
#pragma unroll
        for (int q = 0; q < 4; q++) {
            int ti = half * 64 + tt4 + q;
            float val = ot[ti * 129 + c];
            int ee0 = sre[2 * ti], ee1 = sre[2 * ti + 1];
            val += srw[2 * ti] * b2s[ee0 * 128 + c] + srw[2 * ti + 1] * b2s[ee1 * 128 + c];
            vv[q] = val;
        }
        v.x = vv[0]; v.y = vv[1]; v.z = vv[2]; v.w = vv[3];
        *(float4*)(ob + tt4) = v;
    }
}

// ---------------- load-balance loss -------------------------------------------
__global__ void k_lb(float* __restrict__ out, long long out_size) {
    if (threadIdx.x == 0 && out_size > (long long)BB * CC * NNN) {
        float s = 0.f;
#pragma unroll
        for (int e = 0; e < EE; e++) {
            float u = g_usage[e] * (1.0f / TT);
            s += u * u;
        }
        out[(size_t)BB * CC * NNN] = s * (float)EE;
    }
}

// ---------------- launch --------------------------------------------------------
extern "C" void kernel_launch(void* const* d_in, const int* in_sizes, int n_in,
                              void* d_out, int out_size) {
    const float* x     = (const float*)d_in[0];
    const float* wg1   = (const float*)d_in[1];
    const float* bg1   = (const float*)d_in[2];
    const float* gamma = (const float*)d_in[3];
    const float* beta  = (const float*)d_in[4];
    const float* wg2   = (const float*)d_in[5];
    const float* bg2   = (const float*)d_in[6];
    const float* w1    = (const float*)d_in[7];
    const float* b1    = (const float*)d_in[8];
    const float* w2    = (const float*)d_in[9];
    const float* b2    = (const float*)d_in[10];
    float* out = (float*)d_out;

    cudaFuncSetAttribute(k_gemm,   cudaFuncAttributeMaxDynamicSharedMemorySize, GSMEM);
    cudaFuncSetAttribute(k_egemm1, cudaFuncAttributeMaxDynamicSharedMemorySize, ESMEM);
    cudaFuncSetAttribute(k_egemm2, cudaFuncAttributeMaxDynamicSharedMemorySize, ESMEM);

    k_zero<<<1, 512>>>();
    {
        long long tot4 = ((long long)TT * CC + (long long)CC * CC) / 4;
        int nb = (int)((tot4 + 255) / 256);
        k_split<<<nb, 256>>>(x, wg1);
    }
    k_split2<<<512, 256>>>(w1, w2);
    dim3 gg(CC / 128, TT / 128);
    k_gemm<<<gg, 256, GSMEM>>>(bg1);
    k_egemm1<<<TT / 128, 256, ESMEM>>>(b1);
    k_route<<<TT / 32, 256>>>(gamma, beta, wg2, bg2);
    k_fix<<<256, 256>>>(x, wg1, gamma, beta, wg2, bg2);
    k_scale<<<TT * 128 / 4 / 256, 256>>>();
    dim3 g2(CC / 128, TT / 128);
    k_egemm2<<<g2, 256, ESMEM>>>(b2, out);
    k_lb<<<1, 32>>>(out, (long long)out_size);
}